// round 12
// baseline (speedup 1.0000x reference)
#include <cuda_runtime.h>
#include <cuda_fp16.h>
#include <math.h>
#include <stdint.h>

// Problem dims
#define B_   4
#define S_   4096
#define D_   1024
#define M_   16384
#define CH_  256
#define NCH_ 16

// ---------------- scratch ---------------------------------------------------
__device__ __half g_gated[(size_t)M_ * D_];  // sigmoid(gate)*omega*|iscale| (half)
__device__ __half g_magh [(size_t)M_ * D_];  // magnitude (half)
__device__ float g_phii[(size_t)M_ * D_];    // phi_init, then phi (fp32)
__device__ __half g_xh  [(size_t)M_ * D_];
__device__ __half g_p1h [(size_t)M_ * D_];
__device__ __half g_ctxh[(size_t)M_ * 4 * D_];   // ctx (half), LN in-place
__device__ __half g_h1h [(size_t)M_ * 2 * D_];
__device__ __half g_wh  [5 * (size_t)D_ * D_];   // fused proj B (interleaved) + p2
__device__ __half g_wo1h[(size_t)(2 * D_) * (4 * D_)];
__device__ __half g_wo2h[(size_t)D_ * (2 * D_)];
__device__ float g_gsum [B_ * NCH_ * D_];
__device__ float g_rsum [B_ * NCH_ * D_];
__device__ float g_isum [B_ * NCH_ * D_];
__device__ float g_msum [B_ * NCH_ * D_];

// ---------------- PTX helpers ------------------------------------------------
__device__ __forceinline__ uint32_t smem_u32(const void* p) {
    uint32_t a;
    asm("{ .reg .u64 t; cvta.to.shared.u64 t, %1; cvt.u32.u64 %0, t; }" : "=r"(a) : "l"(p));
    return a;
}

#define CP_ASYNC16(s, g) asm volatile("cp.async.cg.shared.global [%0], [%1], 16;" :: "r"(s), "l"(g) : "memory")
#define CP_COMMIT()      asm volatile("cp.async.commit_group;" ::: "memory")
#define CP_WAIT1()       asm volatile("cp.async.wait_group 1;" ::: "memory")

#define LDSM4(r0, r1, r2, r3, a)                                                \
    asm volatile("ldmatrix.sync.aligned.m8n8.x4.shared.b16 {%0,%1,%2,%3}, [%4];"\
        : "=r"(r0), "=r"(r1), "=r"(r2), "=r"(r3) : "r"(a))

#define MMA16816(d, a, b0, b1)                                                  \
    asm volatile("mma.sync.aligned.m16n8k16.row.col.f32.f16.f16.f32 "           \
        "{%0,%1,%2,%3}, {%4,%5,%6,%7}, {%8,%9}, {%0,%1,%2,%3};"                 \
        : "+f"((d)[0]), "+f"((d)[1]), "+f"((d)[2]), "+f"((d)[3])                \
        : "r"((a)[0]), "r"((a)[1]), "r"((a)[2]), "r"((a)[3]),                   \
          "r"(b0), "r"(b1))

// ---------------- fp16 tensor-core GEMM --------------------------------------
// C = act(A[M,K] @ Bt[N,K]^T + bias) (+res).
// act 4 = gated-pair epilogue (interleaved omega/gate columns) -> half output.
// CTA tile 128x128, K-stage 64, 3 stages (96KB). 8 warps (2M x 4N), warp 64x32.
// XOR-addressed ldmatrix: addr(ks) = base ^ (ks<<5).
#define NSTAGE 3
#define STG_BYTES 32768
#define SMEM_GEMM (NSTAGE * STG_BYTES)

struct Outs {
    float* f[4];
    __half* h[4];
    const float* bias[4];
    int act[4];
};

__global__ __launch_bounds__(256, 2) void mma_gemm(
    const __half* __restrict__ A, const __half* __restrict__ Bt,
    const float* __restrict__ res, Outs o, int K, int N, int blkShift, int outN,
    const float* __restrict__ isc, const float* __restrict__ bias2)
{
    extern __shared__ char smraw[];
    const uint32_t tileBase = smem_u32(smraw);
    const int tid = threadIdx.x;
    const int lane = tid & 31;
    const int wid = tid >> 5;
    const int warpM = wid & 1;
    const int warpN = wid >> 1;
    const int bM = blockIdx.y * 128;
    const int bN = blockIdx.x * 128;
    const int kIters = K >> 6;

    const int lr0 = tid >> 3;
    const int lcc = tid & 7;
    const __half* aSrc0 = A + (size_t)(bM + lr0) * K + lcc * 8;
    const __half* bSrc0 = Bt + (size_t)(bN + lr0) * K + lcc * 8;
    const uint32_t ldst0 = lr0 * 128 + ((lcc ^ (lr0 & 7)) << 4);

    uint32_t pA[4], pB[2];
#pragma unroll
    for (int mt = 0; mt < 4; mt++) {
        const int row = warpM * 64 + mt * 16 + (lane & 15);
        pA[mt] = row * 128 + ((((lane >> 4) ^ row) & 7) << 4);
    }
#pragma unroll
    for (int bt = 0; bt < 2; bt++) {
        const int row = warpN * 32 + bt * 16 + (lane & 7) + ((lane & 16) >> 1);
        pB[bt] = 16384 + row * 128 + (((((lane >> 3) & 1) ^ row) & 7) << 4);
    }

    float acc[4][4][4];
#pragma unroll
    for (int i = 0; i < 4; i++)
#pragma unroll
        for (int j = 0; j < 4; j++)
#pragma unroll
            for (int e = 0; e < 4; e++) acc[i][j][e] = 0.f;

    auto load_stage = [&](int kt, int slot) {
        const uint32_t dst = tileBase + slot * STG_BYTES + ldst0;
        const __half* a = aSrc0 + (kt << 6);
        const __half* b = bSrc0 + (kt << 6);
#pragma unroll
        for (int j = 0; j < 4; j++)
            CP_ASYNC16(dst + j * 4096, a + (size_t)j * 32 * K);
#pragma unroll
        for (int j = 0; j < 4; j++)
            CP_ASYNC16(dst + 16384 + j * 4096, b + (size_t)j * 32 * K);
        CP_COMMIT();
    };

    load_stage(0, 0);
    load_stage(1, 1);

    int slot = 0, slotNxt = 2;
    for (int kt = 0; kt < kIters; kt++) {
        CP_WAIT1();
        __syncthreads();
        if (kt + 2 < kIters) load_stage(kt + 2, slotNxt);

        const uint32_t sBase = tileBase + slot * STG_BYTES;
        uint32_t qA[4], qB[2];
#pragma unroll
        for (int mt = 0; mt < 4; mt++) qA[mt] = sBase + pA[mt];
#pragma unroll
        for (int bt = 0; bt < 2; bt++) qB[bt] = sBase + pB[bt];

#pragma unroll
        for (int ks = 0; ks < 4; ks++) {
            const uint32_t xo = ks << 5;
            uint32_t a[4][4], b[8];
#pragma unroll
            for (int mt = 0; mt < 4; mt++)
                LDSM4(a[mt][0], a[mt][1], a[mt][2], a[mt][3], qA[mt] ^ xo);
#pragma unroll
            for (int bt = 0; bt < 2; bt++)
                LDSM4(b[bt * 4 + 0], b[bt * 4 + 1], b[bt * 4 + 2], b[bt * 4 + 3],
                      qB[bt] ^ xo);
#pragma unroll
            for (int mt = 0; mt < 4; mt++)
#pragma unroll
                for (int nt = 0; nt < 4; nt++)
                    MMA16816(acc[mt][nt], a[mt],
                             b[(nt >> 1) * 4 + (nt & 1) * 2],
                             b[(nt >> 1) * 4 + (nt & 1) * 2 + 1]);
        }
        if (++slot == NSTAGE) slot = 0;
        if (++slotNxt == NSTAGE) slotNxt = 0;
    }

    // epilogue
    int blk = bN >> blkShift;
    if (blk > 3) blk = 3;
    const int act = o.act[blk];
    float* Cf = o.f[blk];
    __half* Ch = o.h[blk];
    const float* bias = o.bias[blk];
    const int colBase = bN & (outN - 1);
    const int g = lane >> 2, q = lane & 3;
#pragma unroll
    for (int mt = 0; mt < 4; mt++) {
#pragma unroll
        for (int nt = 0; nt < 4; nt++) {
            const int cg = warpN * 32 + nt * 8 + q * 2;
            if (act == 4) {
                const int j = (bN + cg) >> 1;
                const float bo = bias[j];
                const float bg = bias2[j];
                const float sc = fabsf(isc[j]);
#pragma unroll
                for (int h = 0; h < 2; h++) {
                    const int row = bM + warpM * 64 + mt * 16 + g + h * 8;
                    const float vo = acc[mt][nt][h * 2 + 0] + bo;
                    const float vg = acc[mt][nt][h * 2 + 1] + bg;
                    const float gt = 1.f / (1.f + expf(-vg));
                    Ch[(size_t)row * outN + j] = __float2half_rn(gt * vo * sc);
                }
                continue;
            }
            const int col = colBase + cg;
            const float b0 = bias[col], b1 = bias[col + 1];
#pragma unroll
            for (int h = 0; h < 2; h++) {
                const int row = bM + warpM * 64 + mt * 16 + g + h * 8;
                float v0 = acc[mt][nt][h * 2 + 0] + b0;
                float v1 = acc[mt][nt][h * 2 + 1] + b1;
                if (act == 1)      { v0 = v0 * normcdff(v0); v1 = v1 * normcdff(v1); }
                else if (act == 2) { v0 = 1.f / (1.f + expf(-v0)); v1 = 1.f / (1.f + expf(-v1)); }
                else if (act == 3) { v0 = 5.f / (1.f + expf(-v0)); v1 = 5.f / (1.f + expf(-v1)); }
                if (res) {
                    v0 += res[(size_t)row * outN + col];
                    v1 += res[(size_t)row * outN + col + 1];
                }
                if (Ch) {
                    *reinterpret_cast<__half2*>(Ch + (size_t)row * outN + col) =
                        __floats2half2_rn(v0, v1);
                } else {
                    *reinterpret_cast<float2*>(Cf + (size_t)row * outN + col) =
                        make_float2(v0, v1);
                }
            }
        }
    }
}

// ---------------- prep kernels -----------------------------------------------
__global__ void f2h_kernel(const float* __restrict__ src,
                           __half* __restrict__ dst, int n)
{
    const int i = blockIdx.x * blockDim.x + threadIdx.x;
    if (i < n) dst[i] = __float2half_rn(src[i]);
}

__global__ void transpose4_h_kernel(const float* __restrict__ wOmega,
                                    const float* __restrict__ wGate,
                                    const float* __restrict__ wMag,
                                    const float* __restrict__ wP1,
                                    __half* __restrict__ Wt)
{
    __shared__ float t[32][33];
    const int z = blockIdx.z;
    const float* W = (z == 0) ? wOmega : (z == 1) ? wGate : (z == 2) ? wMag : wP1;
    const int k0 = blockIdx.y * 32, n0 = blockIdx.x * 32;
    t[threadIdx.y][threadIdx.x] = W[(size_t)(k0 + threadIdx.y) * D_ + n0 + threadIdx.x];
    __syncthreads();
    const int n = n0 + threadIdx.y;
    const int r = (z == 0) ? 2 * n : (z == 1) ? 2 * n + 1
                : (z == 2) ? 2 * D_ + n : 3 * D_ + n;
    Wt[(size_t)r * D_ + k0 + threadIdx.x] =
        __float2half_rn(t[threadIdx.x][threadIdx.y]);
}

__global__ void transpose_h_kernel(const float* __restrict__ W,
                                   __half* __restrict__ Wt, int K, int N)
{
    __shared__ float t[32][33];
    const int k0 = blockIdx.y * 32, n0 = blockIdx.x * 32;
    t[threadIdx.y][threadIdx.x] = W[(size_t)(k0 + threadIdx.y) * N + n0 + threadIdx.x];
    __syncthreads();
    Wt[(size_t)(n0 + threadIdx.y) * K + k0 + threadIdx.x] =
        __float2half_rn(t[threadIdx.x][threadIdx.y]);
}

// ---------------- scan kernels ----------------------------------------------
__global__ void chunk_gsum_kernel(const __half* __restrict__ gated,
                                  float* __restrict__ gsum)
{
    const int t = blockIdx.x * blockDim.x + threadIdx.x;
    if (t >= B_ * NCH_ * D_) return;
    const int d = t % D_;
    const int c = (t / D_) % NCH_;
    const int b = t / (D_ * NCH_);
    size_t idx = ((size_t)(b * S_ + c * CH_)) * D_ + d;
    float sum = 0.f;
    for (int s = 0; s < CH_; s++, idx += D_)
        sum += __half2float(gated[idx]);
    gsum[(b * NCH_ + c) * D_ + d] = sum;
}

__global__ void chunk_scan_kernel(float* __restrict__ v)
{
    const int t = blockIdx.x * blockDim.x + threadIdx.x;
    if (t >= B_ * D_) return;
    const int d = t % D_;
    const int b = t / D_;
    float run = 0.f;
    for (int c = 0; c < NCH_; c++) {
        const int i = (b * NCH_ + c) * D_ + d;
        const float x = v[i];
        v[i] = run;
        run += x;
    }
}

__global__ void chunk_scan3_kernel(float* __restrict__ v0,
                                   float* __restrict__ v1,
                                   float* __restrict__ v2)
{
    const int t = blockIdx.x * blockDim.x + threadIdx.x;
    const int total = B_ * D_;
    if (t >= 3 * total) return;
    float* v = (t < total) ? v0 : (t < 2 * total) ? v1 : v2;
    const int r = t % total;
    const int d = r % D_;
    const int b = r / D_;
    float run = 0.f;
    for (int c = 0; c < NCH_; c++) {
        const int i = (b * NCH_ + c) * D_ + d;
        const float x = v[i];
        v[i] = run;
        run += x;
    }
}

// phase 2: materialize phi (fp32), per-chunk memory sums (half inputs)
__global__ void phi_mem_kernel(const __half* __restrict__ gated,
                               float* __restrict__ phii,   // in: phi_init, out: phi
                               const __half* __restrict__ mag,
                               const __half* __restrict__ xh,
                               const float* __restrict__ gsum,
                               float* __restrict__ rsum,
                               float* __restrict__ isum,
                               float* __restrict__ msum)
{
    const int t = blockIdx.x * blockDim.x + threadIdx.x;
    if (t >= B_ * NCH_ * D_) return;
    const int d = t % D_;
    const int c = (t / D_) % NCH_;
    const int b = t / (D_ * NCH_);
    const int co = (b * NCH_ + c) * D_ + d;

    float run = gsum[co];
    float tR = 0.f, tI = 0.f, tM = 0.f;
    size_t idx = ((size_t)(b * S_ + c * CH_)) * D_ + d;
    for (int s = 0; s < CH_; s++, idx += D_) {
        run += __half2float(gated[idx]);
        const float p = phii[idx] + run;
        phii[idx] = p;
        float sp, cp;
        sincosf(p, &sp, &cp);
        const float mg = __half2float(mag[idx]);
        const float wc = mg * __half2float(xh[idx]);
        tR += wc * cp;
        tI += wc * sp;
        tM += mg;
    }
    rsum[co] = tR;
    isum[co] = tI;
    msum[co] = tM;
}

// ---------------- ctx: 2 d's per thread, recompute sincos --------------------
__global__ void ctx_kernel(const float* __restrict__ phi,
                           const __half* __restrict__ mag,
                           const __half* __restrict__ xh,
                           const float* __restrict__ rsum,
                           const float* __restrict__ isum,
                           const float* __restrict__ msum,
                           __half* __restrict__ ctx)
{
    const int t = blockIdx.x * blockDim.x + threadIdx.x;
    if (t >= B_ * NCH_ * (D_ / 2)) return;
    const int d = (t % (D_ / 2)) * 2;
    const int c = (t / (D_ / 2)) % NCH_;
    const int b = t / ((D_ / 2) * NCH_);
    const int co = (b * NCH_ + c) * D_ + d;

    float R0 = rsum[co], I0 = isum[co], M0 = msum[co];
    float R1 = rsum[co + 1], I1 = isum[co + 1], M1 = msum[co + 1];
    int tok = b * S_ + c * CH_;
    size_t idx = (size_t)tok * D_ + d;
    for (int s = 0; s < CH_; s++, idx += D_, tok++) {
        const float2 ph = *reinterpret_cast<const float2*>(phi + idx);
        const float2 mg = __half22float2(*reinterpret_cast<const __half2*>(mag + idx));
        const float2 xv = __half22float2(*reinterpret_cast<const __half2*>(xh + idx));
        float spx, cpx, spy, cpy;
        sincosf(ph.x, &spx, &cpx);
        sincosf(ph.y, &spy, &cpy);

        R0 += mg.x * xv.x * cpx;  I0 += mg.x * xv.x * spx;  M0 += mg.x;
        R1 += mg.y * xv.y * cpy;  I1 += mg.y * xv.y * spy;  M1 += mg.y;
        const float inv0 = rsqrtf(M0 + 1e-8f);
        const float inv1 = rsqrtf(M1 + 1e-8f);
        const float mr0 = R0 * inv0, mi0 = I0 * inv0;
        const float mr1 = R1 * inv1, mi1 = I1 * inv1;

        const size_t cb = (size_t)tok * (4 * D_);
        *reinterpret_cast<__half2*>(ctx + cb + d) =
            __floats2half2_rn(xv.x * cpx, xv.y * cpy);
        *reinterpret_cast<__half2*>(ctx + cb + D_ + d) =
            __floats2half2_rn(xv.x * spx, xv.y * spy);
        *reinterpret_cast<__half2*>(ctx + cb + 2 * D_ + d) =
            __floats2half2_rn(mr0 * cpx + mi0 * spx, mr1 * cpy + mi1 * spy);
        *reinterpret_cast<__half2*>(ctx + cb + 3 * D_ + d) =
            __floats2half2_rn(mi0 * cpx - mr0 * spx, mi1 * cpy - mr1 * spy);
    }
}

// ---------------- LayerNorm in-place on half buffer --------------------------
__inline__ __device__ float warpSum(float v)
{
#pragma unroll
    for (int o = 16; o; o >>= 1) v += __shfl_xor_sync(0xffffffff, v, o);
    return v;
}

__global__ __launch_bounds__(256) void ln_kernel(__half* __restrict__ ctx,
                                                 const float* __restrict__ gam,
                                                 const float* __restrict__ bet)
{
    const int tok = blockIdx.x;
    __half2* row2 = reinterpret_cast<__half2*>(ctx + (size_t)tok * (4 * D_));
    float s = 0.f, s2 = 0.f;
    for (int i = threadIdx.x; i < 2 * D_; i += 256) {
        const float2 v = __half22float2(row2[i]);
        s += v.x + v.y;
        s2 += v.x * v.x + v.y * v.y;
    }
    s = warpSum(s);
    s2 = warpSum(s2);
    __shared__ float shs[8], shs2[8];
    const int wid = threadIdx.x >> 5, lane = threadIdx.x & 31;
    if (lane == 0) { shs[wid] = s; shs2[wid] = s2; }
    __syncthreads();
    s = 0.f; s2 = 0.f;
#pragma unroll
    for (int w = 0; w < 8; w++) { s += shs[w]; s2 += shs2[w]; }
    const float mu = s * (1.f / (4 * D_));
    const float var = s2 * (1.f / (4 * D_)) - mu * mu;
    const float inv = rsqrtf(var + 1e-5f);
    for (int i = threadIdx.x; i < 2 * D_; i += 256) {
        const float2 v = __half22float2(row2[i]);
        row2[i] = __floats2half2_rn((v.x - mu) * inv * gam[2 * i] + bet[2 * i],
                                    (v.y - mu) * inv * gam[2 * i + 1] + bet[2 * i + 1]);
    }
}

// ---------------- launch ----------------------------------------------------
extern "C" void kernel_launch(void* const* d_in, const int* in_sizes, int n_in,
                              void* d_out, int out_size)
{
    const float* x       = (const float*)d_in[0];
    const float* w_omega = (const float*)d_in[1];
    const float* b_omega = (const float*)d_in[2];
    const float* w_p1    = (const float*)d_in[3];
    const float* b_p1    = (const float*)d_in[4];
    const float* w_p2    = (const float*)d_in[5];
    const float* b_p2    = (const float*)d_in[6];
    const float* w_gate  = (const float*)d_in[7];
    const float* b_gate  = (const float*)d_in[8];
    const float* iscale  = (const float*)d_in[9];
    const float* w_mag   = (const float*)d_in[10];
    const float* b_mag   = (const float*)d_in[11];
    const float* ln_g    = (const float*)d_in[12];
    const float* ln_b    = (const float*)d_in[13];
    const float* w_o1    = (const float*)d_in[14];
    const float* b_o1    = (const float*)d_in[15];
    const float* w_o2    = (const float*)d_in[16];
    const float* b_o2    = (const float*)d_in[17];
    float* out = (float*)d_out;

    float *p_phii, *p_gsum, *p_rsum, *p_isum, *p_msum;
    __half *p_gated, *p_magh, *p_xh, *p_p1h, *p_ctxh, *p_h1h, *p_wh, *p_wo1h, *p_wo2h;
    cudaGetSymbolAddress((void**)&p_gated, g_gated);
    cudaGetSymbolAddress((void**)&p_magh,  g_magh);
    cudaGetSymbolAddress((void**)&p_phii,  g_phii);
    cudaGetSymbolAddress((void**)&p_xh,    g_xh);
    cudaGetSymbolAddress((void**)&p_p1h,   g_p1h);
    cudaGetSymbolAddress((void**)&p_ctxh,  g_ctxh);
    cudaGetSymbolAddress((void**)&p_h1h,   g_h1h);
    cudaGetSymbolAddress((void**)&p_wh,    g_wh);
    cudaGetSymbolAddress((void**)&p_wo1h,  g_wo1h);
    cudaGetSymbolAddress((void**)&p_wo2h,  g_wo2h);
    cudaGetSymbolAddress((void**)&p_gsum,  g_gsum);
    cudaGetSymbolAddress((void**)&p_rsum,  g_rsum);
    cudaGetSymbolAddress((void**)&p_isum,  g_isum);
    cudaGetSymbolAddress((void**)&p_msum,  g_msum);

    static bool attr_set = false;
    if (!attr_set) {
        cudaFuncSetAttribute(mma_gemm, cudaFuncAttributeMaxDynamicSharedMemorySize, SMEM_GEMM);
        attr_set = true;
    }

    const dim3 blk(256);
    const dim3 tb(32, 32);

    // 0: x -> half
    f2h_kernel<<<(M_ * D_) / 256, blk>>>(x, p_xh, M_ * D_);
    // 1: fused interleaved transpose of proj weights
    transpose4_h_kernel<<<dim3(D_ / 32, D_ / 32, 4), tb>>>(w_omega, w_gate, w_mag, w_p1, p_wh);
    // 2: p2 weight
    transpose_h_kernel<<<dim3(D_ / 32, D_ / 32), tb>>>(w_p2, p_wh + 4 * (size_t)D_ * D_, D_, D_);

    // 3: fused projection GEMM: [16384,1024] @ [1024,4096]
    {
        Outs o;
        o.f[0] = nullptr; o.h[0] = p_gated; o.bias[0] = b_omega; o.act[0] = 4;
        o.f[1] = nullptr; o.h[1] = p_gated; o.bias[1] = b_omega; o.act[1] = 4;
        o.f[2] = nullptr; o.h[2] = p_magh;  o.bias[2] = b_mag;   o.act[2] = 3;
        o.f[3] = nullptr; o.h[3] = p_p1h;   o.bias[3] = b_p1;    o.act[3] = 1;
        dim3 g((4 * D_) / 128, M_ / 128);
        mma_gemm<<<g, blk, SMEM_GEMM>>>(p_xh, p_wh, nullptr, o, D_, 4 * D_, 10, D_,
                                        iscale, b_gate);
    }

    // remaining weight prep (off critical path)
    transpose_h_kernel<<<dim3((2 * D_) / 32, (4 * D_) / 32), tb>>>(w_o1, p_wo1h, 4 * D_, 2 * D_);
    transpose_h_kernel<<<dim3(D_ / 32, (2 * D_) / 32), tb>>>(w_o2, p_wo2h, 2 * D_, D_);

    // p2 GEMM -> phi_init (fp32)
    {
        Outs o;
        o.f[0] = p_phii; o.h[0] = nullptr; o.bias[0] = b_p2; o.act[0] = 0;
        o.f[1] = o.f[2] = o.f[3] = nullptr;
        o.h[1] = o.h[2] = o.h[3] = nullptr;
        o.bias[1] = o.bias[2] = o.bias[3] = b_p2;
        o.act[1] = o.act[2] = o.act[3] = 0;
        dim3 g(D_ / 128, M_ / 128);
        mma_gemm<<<g, blk, SMEM_GEMM>>>(p_p1h, p_wh + 4 * (size_t)D_ * D_, nullptr, o,
                                        D_, D_, 30, D_, nullptr, nullptr);
    }

    // --- hierarchical scans ---
    const int nwork = B_ * NCH_ * D_;
    chunk_gsum_kernel<<<nwork / 256, blk>>>(p_gated, p_gsum);
    chunk_scan_kernel<<<(B_ * D_) / 256, blk>>>(p_gsum);
    phi_mem_kernel<<<nwork / 256, blk>>>(p_gated, p_phii, p_magh, p_xh, p_gsum,
                                         p_rsum, p_isum, p_msum);
    chunk_scan3_kernel<<<(3 * B_ * D_) / 256, blk>>>(p_rsum, p_isum, p_msum);
    ctx_kernel<<<(nwork / 2) / 256, blk>>>(p_phii, p_magh, p_xh,
                                           p_rsum, p_isum, p_msum, p_ctxh);

    // --- LayerNorm in place (half) ---
    ln_kernel<<<M_, blk>>>(p_ctxh, ln_g, ln_b);

    // --- output MLP ---
    {
        Outs o1o;
        o1o.f[0] = nullptr; o1o.h[0] = p_h1h; o1o.bias[0] = b_o1; o1o.act[0] = 1;
        o1o.f[1] = o1o.f[2] = o1o.f[3] = nullptr;
        o1o.h[1] = o1o.h[2] = o1o.h[3] = nullptr;
        o1o.bias[1] = o1o.bias[2] = o1o.bias[3] = b_o1;
        o1o.act[1] = o1o.act[2] = o1o.act[3] = 0;
        dim3 g1((2 * D_) / 128, M_ / 128);
        mma_gemm<<<g1, blk, SMEM_GEMM>>>(p_ctxh, p_wo1h, nullptr, o1o, 4 * D_, 2 * D_, 30, 2 * D_,
                                         nullptr, nullptr);

        Outs o2o;
        o2o.f[0] = out; o2o.h[0] = nullptr; o2o.bias[0] = b_o2; o2o.act[0] = 0;
        o2o.f[1] = o2o.f[2] = o2o.f[3] = nullptr;
        o2o.h[1] = o2o.h[2] = o2o.h[3] = nullptr;
        o2o.bias[1] = o2o.bias[2] = o2o.bias[3] = b_o2;
        o2o.act[1] = o2o.act[2] = o2o.act[3] = 0;
        dim3 g2(D_ / 128, M_ / 128);
        mma_gemm<<<g2, blk, SMEM_GEMM>>>(p_h1h, p_wo2h, x, o2o, 2 * D_, D_, 30, D_,
                                         nullptr, nullptr);
    }
}

// round 13
// speedup vs baseline: 1.0902x; 1.0902x over previous
#include <cuda_runtime.h>
#include <cuda_fp16.h>
#include <math.h>
#include <stdint.h>

// Problem dims
#define B_   4
#define S_   4096
#define D_   1024
#define M_   16384
#define CH_  256
#define NCH_ 16

// ---------------- scratch ---------------------------------------------------
__device__ float g_gated[(size_t)M_ * D_];   // sigmoid(gate)*omega*|iscale|
__device__ float g_mag  [(size_t)M_ * D_];
__device__ float g_phii [(size_t)M_ * D_];   // phi_init, then sin(phi)
__device__ float g_cos  [(size_t)M_ * D_];   // cos(phi)
__device__ __half g_xh  [(size_t)M_ * D_];
__device__ __half g_p1h [(size_t)M_ * D_];
__device__ __half g_ctxh[(size_t)M_ * 4 * D_];   // ctx (half), LN in-place
__device__ __half g_h1h [(size_t)M_ * 2 * D_];
__device__ __half g_wh  [5 * (size_t)D_ * D_];   // fused proj B (interleaved) + p2
__device__ __half g_wo1h[(size_t)(2 * D_) * (4 * D_)];
__device__ __half g_wo2h[(size_t)D_ * (2 * D_)];
__device__ float g_gsum [B_ * NCH_ * D_];
__device__ float g_rsum [B_ * NCH_ * D_];
__device__ float g_isum [B_ * NCH_ * D_];
__device__ float g_msum [B_ * NCH_ * D_];

// ---------------- PTX helpers ------------------------------------------------
__device__ __forceinline__ uint32_t smem_u32(const void* p) {
    uint32_t a;
    asm("{ .reg .u64 t; cvta.to.shared.u64 t, %1; cvt.u32.u64 %0, t; }" : "=r"(a) : "l"(p));
    return a;
}

#define CP_ASYNC16(s, g) asm volatile("cp.async.cg.shared.global [%0], [%1], 16;" :: "r"(s), "l"(g) : "memory")
#define CP_COMMIT()      asm volatile("cp.async.commit_group;" ::: "memory")
#define CP_WAIT1()       asm volatile("cp.async.wait_group 1;" ::: "memory")

#define LDSM4(r0, r1, r2, r3, a)                                                \
    asm volatile("ldmatrix.sync.aligned.m8n8.x4.shared.b16 {%0,%1,%2,%3}, [%4];"\
        : "=r"(r0), "=r"(r1), "=r"(r2), "=r"(r3) : "r"(a))

#define MMA16816(d, a, b0, b1)                                                  \
    asm volatile("mma.sync.aligned.m16n8k16.row.col.f32.f16.f16.f32 "           \
        "{%0,%1,%2,%3}, {%4,%5,%6,%7}, {%8,%9}, {%0,%1,%2,%3};"                 \
        : "+f"((d)[0]), "+f"((d)[1]), "+f"((d)[2]), "+f"((d)[3])                \
        : "r"((a)[0]), "r"((a)[1]), "r"((a)[2]), "r"((a)[3]),                   \
          "r"(b0), "r"(b1))

// ---------------- fp16 tensor-core GEMM --------------------------------------
// C = act(A[M,K] @ Bt[N,K]^T + bias) (+res).
// act 4 = gated-pair epilogue (interleaved omega/gate columns).
// CTA tile 128x128, K-stage 64, 3 stages (96KB). 8 warps (2M x 4N), warp 64x32.
// XOR-addressed ldmatrix: addr(ks) = base ^ (ks<<5).
#define NSTAGE 3
#define STG_BYTES 32768
#define SMEM_GEMM (NSTAGE * STG_BYTES)

struct Outs {
    float* f[4];
    __half* h[4];
    const float* bias[4];
    int act[4];
};

__global__ __launch_bounds__(256, 2) void mma_gemm(
    const __half* __restrict__ A, const __half* __restrict__ Bt,
    const float* __restrict__ res, Outs o, int K, int N, int blkShift, int outN,
    const float* __restrict__ isc, const float* __restrict__ bias2)
{
    extern __shared__ char smraw[];
    const uint32_t tileBase = smem_u32(smraw);
    const int tid = threadIdx.x;
    const int lane = tid & 31;
    const int wid = tid >> 5;
    const int warpM = wid & 1;
    const int warpN = wid >> 1;
    const int bM = blockIdx.y * 128;
    const int bN = blockIdx.x * 128;
    const int kIters = K >> 6;

    const int lr0 = tid >> 3;
    const int lcc = tid & 7;
    const __half* aSrc0 = A + (size_t)(bM + lr0) * K + lcc * 8;
    const __half* bSrc0 = Bt + (size_t)(bN + lr0) * K + lcc * 8;
    const uint32_t ldst0 = lr0 * 128 + ((lcc ^ (lr0 & 7)) << 4);

    uint32_t pA[4], pB[2];
#pragma unroll
    for (int mt = 0; mt < 4; mt++) {
        const int row = warpM * 64 + mt * 16 + (lane & 15);
        pA[mt] = row * 128 + ((((lane >> 4) ^ row) & 7) << 4);
    }
#pragma unroll
    for (int bt = 0; bt < 2; bt++) {
        const int row = warpN * 32 + bt * 16 + (lane & 7) + ((lane & 16) >> 1);
        pB[bt] = 16384 + row * 128 + (((((lane >> 3) & 1) ^ row) & 7) << 4);
    }

    float acc[4][4][4];
#pragma unroll
    for (int i = 0; i < 4; i++)
#pragma unroll
        for (int j = 0; j < 4; j++)
#pragma unroll
            for (int e = 0; e < 4; e++) acc[i][j][e] = 0.f;

    auto load_stage = [&](int kt, int slot) {
        const uint32_t dst = tileBase + slot * STG_BYTES + ldst0;
        const __half* a = aSrc0 + (kt << 6);
        const __half* b = bSrc0 + (kt << 6);
#pragma unroll
        for (int j = 0; j < 4; j++)
            CP_ASYNC16(dst + j * 4096, a + (size_t)j * 32 * K);
#pragma unroll
        for (int j = 0; j < 4; j++)
            CP_ASYNC16(dst + 16384 + j * 4096, b + (size_t)j * 32 * K);
        CP_COMMIT();
    };

    load_stage(0, 0);
    load_stage(1, 1);

    int slot = 0, slotNxt = 2;
    for (int kt = 0; kt < kIters; kt++) {
        CP_WAIT1();
        __syncthreads();
        if (kt + 2 < kIters) load_stage(kt + 2, slotNxt);

        const uint32_t sBase = tileBase + slot * STG_BYTES;
        uint32_t qA[4], qB[2];
#pragma unroll
        for (int mt = 0; mt < 4; mt++) qA[mt] = sBase + pA[mt];
#pragma unroll
        for (int bt = 0; bt < 2; bt++) qB[bt] = sBase + pB[bt];

#pragma unroll
        for (int ks = 0; ks < 4; ks++) {
            const uint32_t xo = ks << 5;
            uint32_t a[4][4], b[8];
#pragma unroll
            for (int mt = 0; mt < 4; mt++)
                LDSM4(a[mt][0], a[mt][1], a[mt][2], a[mt][3], qA[mt] ^ xo);
#pragma unroll
            for (int bt = 0; bt < 2; bt++)
                LDSM4(b[bt * 4 + 0], b[bt * 4 + 1], b[bt * 4 + 2], b[bt * 4 + 3],
                      qB[bt] ^ xo);
#pragma unroll
            for (int mt = 0; mt < 4; mt++)
#pragma unroll
                for (int nt = 0; nt < 4; nt++)
                    MMA16816(acc[mt][nt], a[mt],
                             b[(nt >> 1) * 4 + (nt & 1) * 2],
                             b[(nt >> 1) * 4 + (nt & 1) * 2 + 1]);
        }
        if (++slot == NSTAGE) slot = 0;
        if (++slotNxt == NSTAGE) slotNxt = 0;
    }

    // epilogue
    int blk = bN >> blkShift;
    if (blk > 3) blk = 3;
    const int act = o.act[blk];
    float* Cf = o.f[blk];
    __half* Ch = o.h[blk];
    const float* bias = o.bias[blk];
    const int colBase = bN & (outN - 1);
    const int g = lane >> 2, q = lane & 3;
#pragma unroll
    for (int mt = 0; mt < 4; mt++) {
#pragma unroll
        for (int nt = 0; nt < 4; nt++) {
            const int cg = warpN * 32 + nt * 8 + q * 2;
            if (act == 4) {
                const int j = (bN + cg) >> 1;
                const float bo = bias[j];
                const float bg = bias2[j];
                const float sc = fabsf(isc[j]);
#pragma unroll
                for (int h = 0; h < 2; h++) {
                    const int row = bM + warpM * 64 + mt * 16 + g + h * 8;
                    const float vo = acc[mt][nt][h * 2 + 0] + bo;
                    const float vg = acc[mt][nt][h * 2 + 1] + bg;
                    const float gt = 1.f / (1.f + expf(-vg));
                    Cf[(size_t)row * outN + j] = gt * vo * sc;
                }
                continue;
            }
            const int col = colBase + cg;
            const float b0 = bias[col], b1 = bias[col + 1];
#pragma unroll
            for (int h = 0; h < 2; h++) {
                const int row = bM + warpM * 64 + mt * 16 + g + h * 8;
                float v0 = acc[mt][nt][h * 2 + 0] + b0;
                float v1 = acc[mt][nt][h * 2 + 1] + b1;
                if (act == 1)      { v0 = v0 * normcdff(v0); v1 = v1 * normcdff(v1); }
                else if (act == 2) { v0 = 1.f / (1.f + expf(-v0)); v1 = 1.f / (1.f + expf(-v1)); }
                else if (act == 3) { v0 = 5.f / (1.f + expf(-v0)); v1 = 5.f / (1.f + expf(-v1)); }
                if (res) {
                    v0 += res[(size_t)row * outN + col];
                    v1 += res[(size_t)row * outN + col + 1];
                }
                if (Ch) {
                    *reinterpret_cast<__half2*>(Ch + (size_t)row * outN + col) =
                        __floats2half2_rn(v0, v1);
                } else {
                    *reinterpret_cast<float2*>(Cf + (size_t)row * outN + col) =
                        make_float2(v0, v1);
                }
            }
        }
    }
}

// ---------------- prep kernels -----------------------------------------------
__global__ void f2h_kernel(const float* __restrict__ src,
                           __half* __restrict__ dst, int n)
{
    const int i = blockIdx.x * blockDim.x + threadIdx.x;
    if (i < n) dst[i] = __float2half_rn(src[i]);
}

__global__ void transpose4_h_kernel(const float* __restrict__ wOmega,
                                    const float* __restrict__ wGate,
                                    const float* __restrict__ wMag,
                                    const float* __restrict__ wP1,
                                    __half* __restrict__ Wt)
{
    __shared__ float t[32][33];
    const int z = blockIdx.z;
    const float* W = (z == 0) ? wOmega : (z == 1) ? wGate : (z == 2) ? wMag : wP1;
    const int k0 = blockIdx.y * 32, n0 = blockIdx.x * 32;
    t[threadIdx.y][threadIdx.x] = W[(size_t)(k0 + threadIdx.y) * D_ + n0 + threadIdx.x];
    __syncthreads();
    const int n = n0 + threadIdx.y;
    const int r = (z == 0) ? 2 * n : (z == 1) ? 2 * n + 1
                : (z == 2) ? 2 * D_ + n : 3 * D_ + n;
    Wt[(size_t)r * D_ + k0 + threadIdx.x] =
        __float2half_rn(t[threadIdx.x][threadIdx.y]);
}

__global__ void transpose_h_kernel(const float* __restrict__ W,
                                   __half* __restrict__ Wt, int K, int N)
{
    __shared__ float t[32][33];
    const int k0 = blockIdx.y * 32, n0 = blockIdx.x * 32;
    t[threadIdx.y][threadIdx.x] = W[(size_t)(k0 + threadIdx.y) * N + n0 + threadIdx.x];
    __syncthreads();
    Wt[(size_t)(n0 + threadIdx.y) * K + k0 + threadIdx.x] =
        __float2half_rn(t[threadIdx.x][threadIdx.y]);
}

// ---------------- scan kernels ----------------------------------------------
// float2: 2 d's per thread
__global__ void chunk_gsum_kernel(const float* __restrict__ gated,
                                  float* __restrict__ gsum)
{
    const int t = blockIdx.x * blockDim.x + threadIdx.x;
    if (t >= B_ * NCH_ * (D_ / 2)) return;
    const int d = (t % (D_ / 2)) * 2;
    const int c = (t / (D_ / 2)) % NCH_;
    const int b = t / ((D_ / 2) * NCH_);
    size_t idx = ((size_t)(b * S_ + c * CH_)) * D_ + d;
    float s0 = 0.f, s1 = 0.f;
    for (int s = 0; s < CH_; s++, idx += D_) {
        const float2 v = *reinterpret_cast<const float2*>(gated + idx);
        s0 += v.x;
        s1 += v.y;
    }
    const int co = (b * NCH_ + c) * D_ + d;
    gsum[co] = s0;
    gsum[co + 1] = s1;
}

__global__ void chunk_scan_kernel(float* __restrict__ v)
{
    const int t = blockIdx.x * blockDim.x + threadIdx.x;
    if (t >= B_ * D_) return;
    const int d = t % D_;
    const int b = t / D_;
    float run = 0.f;
    for (int c = 0; c < NCH_; c++) {
        const int i = (b * NCH_ + c) * D_ + d;
        const float x = v[i];
        v[i] = run;
        run += x;
    }
}

__global__ void chunk_scan3_kernel(float* __restrict__ v0,
                                   float* __restrict__ v1,
                                   float* __restrict__ v2)
{
    const int t = blockIdx.x * blockDim.x + threadIdx.x;
    const int total = B_ * D_;
    if (t >= 3 * total) return;
    float* v = (t < total) ? v0 : (t < 2 * total) ? v1 : v2;
    const int r = t % total;
    const int d = r % D_;
    const int b = r / D_;
    float run = 0.f;
    for (int c = 0; c < NCH_; c++) {
        const int i = (b * NCH_ + c) * D_ + d;
        const float x = v[i];
        v[i] = run;
        run += x;
    }
}

// phase 2: materialize cos/sin(phi) (fast sincos), per-chunk memory sums
__global__ void phi_mem_kernel(const float* __restrict__ gated,
                               float* __restrict__ phii,   // in: phi_init, out: sin(phi)
                               const float* __restrict__ mag,
                               const float* __restrict__ x,
                               const float* __restrict__ gsum,
                               float* __restrict__ cosphi,
                               float* __restrict__ rsum,
                               float* __restrict__ isum,
                               float* __restrict__ msum)
{
    const int t = blockIdx.x * blockDim.x + threadIdx.x;
    if (t >= B_ * NCH_ * D_) return;
    const int d = t % D_;
    const int c = (t / D_) % NCH_;
    const int b = t / (D_ * NCH_);
    const int co = (b * NCH_ + c) * D_ + d;

    float run = gsum[co];
    float tR = 0.f, tI = 0.f, tM = 0.f;
    size_t idx = ((size_t)(b * S_ + c * CH_)) * D_ + d;
    for (int s = 0; s < CH_; s++, idx += D_) {
        run += gated[idx];
        const float p = phii[idx] + run;
        float sp, cp;
        __sincosf(p, &sp, &cp);
        cosphi[idx] = cp;
        phii[idx] = sp;
        const float mg = mag[idx];
        const float wc = mg * x[idx];
        tR += wc * cp;
        tI += wc * sp;
        tM += mg;
    }
    rsum[co] = tR;
    isum[co] = tI;
    msum[co] = tM;
}

// ---------------- ctx: 2 d's per thread, half2 stores ------------------------
__global__ void ctx_kernel(const float* __restrict__ cosphi,
                           const float* __restrict__ sinphi,
                           const float* __restrict__ mag,
                           const float* __restrict__ x,
                           const float* __restrict__ rsum,
                           const float* __restrict__ isum,
                           const float* __restrict__ msum,
                           __half* __restrict__ ctx)
{
    const int t = blockIdx.x * blockDim.x + threadIdx.x;
    if (t >= B_ * NCH_ * (D_ / 2)) return;
    const int d = (t % (D_ / 2)) * 2;
    const int c = (t / (D_ / 2)) % NCH_;
    const int b = t / ((D_ / 2) * NCH_);
    const int co = (b * NCH_ + c) * D_ + d;

    float R0 = rsum[co], I0 = isum[co], M0 = msum[co];
    float R1 = rsum[co + 1], I1 = isum[co + 1], M1 = msum[co + 1];
    int tok = b * S_ + c * CH_;
    size_t idx = (size_t)tok * D_ + d;
    for (int s = 0; s < CH_; s++, idx += D_, tok++) {
        const float2 cp = *reinterpret_cast<const float2*>(cosphi + idx);
        const float2 sp = *reinterpret_cast<const float2*>(sinphi + idx);
        const float2 mg = *reinterpret_cast<const float2*>(mag + idx);
        const float2 xv = *reinterpret_cast<const float2*>(x + idx);

        R0 += mg.x * xv.x * cp.x;  I0 += mg.x * xv.x * sp.x;  M0 += mg.x;
        R1 += mg.y * xv.y * cp.y;  I1 += mg.y * xv.y * sp.y;  M1 += mg.y;
        const float inv0 = rsqrtf(M0 + 1e-8f);
        const float inv1 = rsqrtf(M1 + 1e-8f);
        const float mr0 = R0 * inv0, mi0 = I0 * inv0;
        const float mr1 = R1 * inv1, mi1 = I1 * inv1;

        const size_t cb = (size_t)tok * (4 * D_);
        *reinterpret_cast<__half2*>(ctx + cb + d) =
            __floats2half2_rn(xv.x * cp.x, xv.y * cp.y);
        *reinterpret_cast<__half2*>(ctx + cb + D_ + d) =
            __floats2half2_rn(xv.x * sp.x, xv.y * sp.y);
        *reinterpret_cast<__half2*>(ctx + cb + 2 * D_ + d) =
            __floats2half2_rn(mr0 * cp.x + mi0 * sp.x, mr1 * cp.y + mi1 * sp.y);
        *reinterpret_cast<__half2*>(ctx + cb + 3 * D_ + d) =
            __floats2half2_rn(mi0 * cp.x - mr0 * sp.x, mi1 * cp.y - mr1 * sp.y);
    }
}

// ---------------- LayerNorm in-place on half buffer --------------------------
__inline__ __device__ float warpSum(float v)
{
#pragma unroll
    for (int o = 16; o; o >>= 1) v += __shfl_xor_sync(0xffffffff, v, o);
    return v;
}

__global__ __launch_bounds__(256) void ln_kernel(__half* __restrict__ ctx,
                                                 const float* __restrict__ gam,
                                                 const float* __restrict__ bet)
{
    const int tok = blockIdx.x;
    __half2* row2 = reinterpret_cast<__half2*>(ctx + (size_t)tok * (4 * D_));
    float s = 0.f, s2 = 0.f;
    for (int i = threadIdx.x; i < 2 * D_; i += 256) {
        const float2 v = __half22float2(row2[i]);
        s += v.x + v.y;
        s2 += v.x * v.x + v.y * v.y;
    }
    s = warpSum(s);
    s2 = warpSum(s2);
    __shared__ float shs[8], shs2[8];
    const int wid = threadIdx.x >> 5, lane = threadIdx.x & 31;
    if (lane == 0) { shs[wid] = s; shs2[wid] = s2; }
    __syncthreads();
    s = 0.f; s2 = 0.f;
#pragma unroll
    for (int w = 0; w < 8; w++) { s += shs[w]; s2 += shs2[w]; }
    const float mu = s * (1.f / (4 * D_));
    const float var = s2 * (1.f / (4 * D_)) - mu * mu;
    const float inv = rsqrtf(var + 1e-5f);
    for (int i = threadIdx.x; i < 2 * D_; i += 256) {
        const float2 v = __half22float2(row2[i]);
        row2[i] = __floats2half2_rn((v.x - mu) * inv * gam[2 * i] + bet[2 * i],
                                    (v.y - mu) * inv * gam[2 * i + 1] + bet[2 * i + 1]);
    }
}

// ---------------- launch ----------------------------------------------------
extern "C" void kernel_launch(void* const* d_in, const int* in_sizes, int n_in,
                              void* d_out, int out_size)
{
    const float* x       = (const float*)d_in[0];
    const float* w_omega = (const float*)d_in[1];
    const float* b_omega = (const float*)d_in[2];
    const float* w_p1    = (const float*)d_in[3];
    const float* b_p1    = (const float*)d_in[4];
    const float* w_p2    = (const float*)d_in[5];
    const float* b_p2    = (const float*)d_in[6];
    const float* w_gate  = (const float*)d_in[7];
    const float* b_gate  = (const float*)d_in[8];
    const float* iscale  = (const float*)d_in[9];
    const float* w_mag   = (const float*)d_in[10];
    const float* b_mag   = (const float*)d_in[11];
    const float* ln_g    = (const float*)d_in[12];
    const float* ln_b    = (const float*)d_in[13];
    const float* w_o1    = (const float*)d_in[14];
    const float* b_o1    = (const float*)d_in[15];
    const float* w_o2    = (const float*)d_in[16];
    const float* b_o2    = (const float*)d_in[17];
    float* out = (float*)d_out;

    float *p_gated, *p_mag, *p_phii, *p_cos;
    float *p_gsum, *p_rsum, *p_isum, *p_msum;
    __half *p_xh, *p_p1h, *p_ctxh, *p_h1h, *p_wh, *p_wo1h, *p_wo2h;
    cudaGetSymbolAddress((void**)&p_gated, g_gated);
    cudaGetSymbolAddress((void**)&p_mag,   g_mag);
    cudaGetSymbolAddress((void**)&p_phii,  g_phii);
    cudaGetSymbolAddress((void**)&p_cos,   g_cos);
    cudaGetSymbolAddress((void**)&p_xh,    g_xh);
    cudaGetSymbolAddress((void**)&p_p1h,   g_p1h);
    cudaGetSymbolAddress((void**)&p_ctxh,  g_ctxh);
    cudaGetSymbolAddress((void**)&p_h1h,   g_h1h);
    cudaGetSymbolAddress((void**)&p_wh,    g_wh);
    cudaGetSymbolAddress((void**)&p_wo1h,  g_wo1h);
    cudaGetSymbolAddress((void**)&p_wo2h,  g_wo2h);
    cudaGetSymbolAddress((void**)&p_gsum,  g_gsum);
    cudaGetSymbolAddress((void**)&p_rsum,  g_rsum);
    cudaGetSymbolAddress((void**)&p_isum,  g_isum);
    cudaGetSymbolAddress((void**)&p_msum,  g_msum);

    static bool attr_set = false;
    if (!attr_set) {
        cudaFuncSetAttribute(mma_gemm, cudaFuncAttributeMaxDynamicSharedMemorySize, SMEM_GEMM);
        attr_set = true;
    }

    const dim3 blk(256);
    const dim3 tb(32, 32);

    // 0: x -> half
    f2h_kernel<<<(M_ * D_) / 256, blk>>>(x, p_xh, M_ * D_);
    // 1: fused interleaved transpose of proj weights
    transpose4_h_kernel<<<dim3(D_ / 32, D_ / 32, 4), tb>>>(w_omega, w_gate, w_mag, w_p1, p_wh);
    // 2: p2 weight
    transpose_h_kernel<<<dim3(D_ / 32, D_ / 32), tb>>>(w_p2, p_wh + 4 * (size_t)D_ * D_, D_, D_);

    // 3: fused projection GEMM: [16384,1024] @ [1024,4096]
    {
        Outs o;
        o.f[0] = p_gated; o.h[0] = nullptr; o.bias[0] = b_omega; o.act[0] = 4;
        o.f[1] = p_gated; o.h[1] = nullptr; o.bias[1] = b_omega; o.act[1] = 4;
        o.f[2] = p_mag;   o.h[2] = nullptr; o.bias[2] = b_mag;   o.act[2] = 3;
        o.f[3] = nullptr; o.h[3] = p_p1h;   o.bias[3] = b_p1;    o.act[3] = 1;
        dim3 g((4 * D_) / 128, M_ / 128);
        mma_gemm<<<g, blk, SMEM_GEMM>>>(p_xh, p_wh, nullptr, o, D_, 4 * D_, 10, D_,
                                        iscale, b_gate);
    }

    // remaining weight prep (off critical path)
    transpose_h_kernel<<<dim3((2 * D_) / 32, (4 * D_) / 32), tb>>>(w_o1, p_wo1h, 4 * D_, 2 * D_);
    transpose_h_kernel<<<dim3(D_ / 32, (2 * D_) / 32), tb>>>(w_o2, p_wo2h, 2 * D_, D_);

    // p2 GEMM
    {
        Outs o;
        o.f[0] = p_phii; o.h[0] = nullptr; o.bias[0] = b_p2; o.act[0] = 0;
        o.f[1] = o.f[2] = o.f[3] = nullptr;
        o.h[1] = o.h[2] = o.h[3] = nullptr;
        o.bias[1] = o.bias[2] = o.bias[3] = b_p2;
        o.act[1] = o.act[2] = o.act[3] = 0;
        dim3 g(D_ / 128, M_ / 128);
        mma_gemm<<<g, blk, SMEM_GEMM>>>(p_p1h, p_wh + 4 * (size_t)D_ * D_, nullptr, o,
                                        D_, D_, 30, D_, nullptr, nullptr);
    }

    // --- hierarchical scans ---
    const int nwork = B_ * NCH_ * D_;
    chunk_gsum_kernel<<<(nwork / 2) / 256, blk>>>(p_gated, p_gsum);
    chunk_scan_kernel<<<(B_ * D_) / 256, blk>>>(p_gsum);
    phi_mem_kernel<<<nwork / 256, blk>>>(p_gated, p_phii, p_mag, x, p_gsum,
                                         p_cos, p_rsum, p_isum, p_msum);
    chunk_scan3_kernel<<<(3 * B_ * D_) / 256, blk>>>(p_rsum, p_isum, p_msum);
    ctx_kernel<<<(nwork / 2) / 256, blk>>>(p_cos, p_phii, p_mag, x,
                                           p_rsum, p_isum, p_msum, p_ctxh);

    // --- LayerNorm in place (half) ---
    ln_kernel<<<M_, blk>>>(p_ctxh, ln_g, ln_b);

    // --- output MLP ---
    {
        Outs o1o;
        o1o.f[0] = nullptr; o1o.h[0] = p_h1h; o1o.bias[0] = b_o1; o1o.act[0] = 1;
        o1o.f[1] = o1o.f[2] = o1o.f[3] = nullptr;
        o1o.h[1] = o1o.h[2] = o1o.h[3] = nullptr;
        o1o.bias[1] = o1o.bias[2] = o1o.bias[3] = b_o1;
        o1o.act[1] = o1o.act[2] = o1o.act[3] = 0;
        dim3 g1((2 * D_) / 128, M_ / 128);
        mma_gemm<<<g1, blk, SMEM_GEMM>>>(p_ctxh, p_wo1h, nullptr, o1o, 4 * D_, 2 * D_, 30, 2 * D_,
                                         nullptr, nullptr);

        Outs o2o;
        o2o.f[0] = out; o2o.h[0] = nullptr; o2o.bias[0] = b_o2; o2o.act[0] = 0;
        o2o.f[1] = o2o.f[2] = o2o.f[3] = nullptr;
        o2o.h[1] = o2o.h[2] = o2o.h[3] = nullptr;
        o2o.bias[1] = o2o.bias[2] = o2o.bias[3] = b_o2;
        o2o.act[1] = o2o.act[2] = o2o.act[3] = 0;
        dim3 g2(D_ / 128, M_ / 128);
        mma_gemm<<<g2, blk, SMEM_GEMM>>>(p_h1h, p_wo2h, x, o2o, 2 * D_, D_, 30, D_,
                                         nullptr, nullptr);
    }
}

// round 14
// speedup vs baseline: 1.0941x; 1.0036x over previous
#include <cuda_runtime.h>
#include <cuda_fp16.h>
#include <math.h>
#include <stdint.h>

// Problem dims
#define B_   4
#define S_   4096
#define D_   1024
#define M_   16384
#define CH_  256
#define NCH_ 16

// ---------------- scratch ---------------------------------------------------
__device__ float g_gated[(size_t)M_ * D_];   // sigmoid(gate)*omega*|iscale|
__device__ float g_mag  [(size_t)M_ * D_];
__device__ float g_phii [(size_t)M_ * D_];   // phi_init, then sin(phi)
__device__ float g_cos  [(size_t)M_ * D_];   // cos(phi)
__device__ __half g_xh  [(size_t)M_ * D_];
__device__ __half g_p1h [(size_t)M_ * D_];
__device__ __half g_ctxh[(size_t)M_ * 4 * D_];   // ctx (half), LN in-place
__device__ __half g_h1h [(size_t)M_ * 2 * D_];
__device__ __half g_wh  [5 * (size_t)D_ * D_];   // fused proj B (interleaved) + p2
__device__ __half g_wo1h[(size_t)(2 * D_) * (4 * D_)];
__device__ __half g_wo2h[(size_t)D_ * (2 * D_)];
__device__ float g_gsum [B_ * NCH_ * D_];
__device__ float g_rsum [B_ * NCH_ * D_];
__device__ float g_isum [B_ * NCH_ * D_];
__device__ float g_msum [B_ * NCH_ * D_];

// ---------------- PTX helpers ------------------------------------------------
__device__ __forceinline__ uint32_t smem_u32(const void* p) {
    uint32_t a;
    asm("{ .reg .u64 t; cvta.to.shared.u64 t, %1; cvt.u32.u64 %0, t; }" : "=r"(a) : "l"(p));
    return a;
}

__device__ __forceinline__ float fast_sigmoid(float v) {
    return 1.f / (1.f + __expf(-v));
}

#define CP_ASYNC16(s, g) asm volatile("cp.async.cg.shared.global [%0], [%1], 16;" :: "r"(s), "l"(g) : "memory")
#define CP_COMMIT()      asm volatile("cp.async.commit_group;" ::: "memory")
#define CP_WAIT1()       asm volatile("cp.async.wait_group 1;" ::: "memory")

#define LDSM4(r0, r1, r2, r3, a)                                                \
    asm volatile("ldmatrix.sync.aligned.m8n8.x4.shared.b16 {%0,%1,%2,%3}, [%4];"\
        : "=r"(r0), "=r"(r1), "=r"(r2), "=r"(r3) : "r"(a))

#define MMA16816(d, a, b0, b1)                                                  \
    asm volatile("mma.sync.aligned.m16n8k16.row.col.f32.f16.f16.f32 "           \
        "{%0,%1,%2,%3}, {%4,%5,%6,%7}, {%8,%9}, {%0,%1,%2,%3};"                 \
        : "+f"((d)[0]), "+f"((d)[1]), "+f"((d)[2]), "+f"((d)[3])                \
        : "r"((a)[0]), "r"((a)[1]), "r"((a)[2]), "r"((a)[3]),                   \
          "r"(b0), "r"(b1))

// ---------------- fp16 tensor-core GEMM --------------------------------------
// C = act(A[M,K] @ Bt[N,K]^T + bias) (+res).
// act 4 = gated-pair epilogue (interleaved omega/gate columns).
// CTA tile 128x128, K-stage 64, 3 stages (96KB). 8 warps (2M x 4N), warp 64x32.
// XOR-addressed ldmatrix: addr(ks) = base ^ (ks<<5).
#define NSTAGE 3
#define STG_BYTES 32768
#define SMEM_GEMM (NSTAGE * STG_BYTES)

struct Outs {
    float* f[4];
    __half* h[4];
    const float* bias[4];
    int act[4];
};

__global__ __launch_bounds__(256, 2) void mma_gemm(
    const __half* __restrict__ A, const __half* __restrict__ Bt,
    const float* __restrict__ res, Outs o, int K, int N, int blkShift, int outN,
    const float* __restrict__ isc, const float* __restrict__ bias2)
{
    extern __shared__ char smraw[];
    const uint32_t tileBase = smem_u32(smraw);
    const int tid = threadIdx.x;
    const int lane = tid & 31;
    const int wid = tid >> 5;
    const int warpM = wid & 1;
    const int warpN = wid >> 1;
    const int bM = blockIdx.y * 128;
    const int bN = blockIdx.x * 128;
    const int kIters = K >> 6;

    const int lr0 = tid >> 3;
    const int lcc = tid & 7;
    const __half* aSrc0 = A + (size_t)(bM + lr0) * K + lcc * 8;
    const __half* bSrc0 = Bt + (size_t)(bN + lr0) * K + lcc * 8;
    const uint32_t ldst0 = lr0 * 128 + ((lcc ^ (lr0 & 7)) << 4);

    uint32_t pA[4], pB[2];
#pragma unroll
    for (int mt = 0; mt < 4; mt++) {
        const int row = warpM * 64 + mt * 16 + (lane & 15);
        pA[mt] = row * 128 + ((((lane >> 4) ^ row) & 7) << 4);
    }
#pragma unroll
    for (int bt = 0; bt < 2; bt++) {
        const int row = warpN * 32 + bt * 16 + (lane & 7) + ((lane & 16) >> 1);
        pB[bt] = 16384 + row * 128 + (((((lane >> 3) & 1) ^ row) & 7) << 4);
    }

    float acc[4][4][4];
#pragma unroll
    for (int i = 0; i < 4; i++)
#pragma unroll
        for (int j = 0; j < 4; j++)
#pragma unroll
            for (int e = 0; e < 4; e++) acc[i][j][e] = 0.f;

    auto load_stage = [&](int kt, int slot) {
        const uint32_t dst = tileBase + slot * STG_BYTES + ldst0;
        const __half* a = aSrc0 + (kt << 6);
        const __half* b = bSrc0 + (kt << 6);
#pragma unroll
        for (int j = 0; j < 4; j++)
            CP_ASYNC16(dst + j * 4096, a + (size_t)j * 32 * K);
#pragma unroll
        for (int j = 0; j < 4; j++)
            CP_ASYNC16(dst + 16384 + j * 4096, b + (size_t)j * 32 * K);
        CP_COMMIT();
    };

    load_stage(0, 0);
    load_stage(1, 1);

    int slot = 0, slotNxt = 2;
    for (int kt = 0; kt < kIters; kt++) {
        CP_WAIT1();
        __syncthreads();
        if (kt + 2 < kIters) load_stage(kt + 2, slotNxt);

        const uint32_t sBase = tileBase + slot * STG_BYTES;
        uint32_t qA[4], qB[2];
#pragma unroll
        for (int mt = 0; mt < 4; mt++) qA[mt] = sBase + pA[mt];
#pragma unroll
        for (int bt = 0; bt < 2; bt++) qB[bt] = sBase + pB[bt];

#pragma unroll
        for (int ks = 0; ks < 4; ks++) {
            const uint32_t xo = ks << 5;
            uint32_t a[4][4], b[8];
#pragma unroll
            for (int mt = 0; mt < 4; mt++)
                LDSM4(a[mt][0], a[mt][1], a[mt][2], a[mt][3], qA[mt] ^ xo);
#pragma unroll
            for (int bt = 0; bt < 2; bt++)
                LDSM4(b[bt * 4 + 0], b[bt * 4 + 1], b[bt * 4 + 2], b[bt * 4 + 3],
                      qB[bt] ^ xo);
#pragma unroll
            for (int mt = 0; mt < 4; mt++)
#pragma unroll
                for (int nt = 0; nt < 4; nt++)
                    MMA16816(acc[mt][nt], a[mt],
                             b[(nt >> 1) * 4 + (nt & 1) * 2],
                             b[(nt >> 1) * 4 + (nt & 1) * 2 + 1]);
        }
        if (++slot == NSTAGE) slot = 0;
        if (++slotNxt == NSTAGE) slotNxt = 0;
    }

    // epilogue
    int blk = bN >> blkShift;
    if (blk > 3) blk = 3;
    const int act = o.act[blk];
    float* Cf = o.f[blk];
    __half* Ch = o.h[blk];
    const float* bias = o.bias[blk];
    const int colBase = bN & (outN - 1);
    const int g = lane >> 2, q = lane & 3;
#pragma unroll
    for (int mt = 0; mt < 4; mt++) {
#pragma unroll
        for (int nt = 0; nt < 4; nt++) {
            const int cg = warpN * 32 + nt * 8 + q * 2;
            if (act == 4) {
                const int j = (bN + cg) >> 1;
                const float bo = bias[j];
                const float bg = bias2[j];
                const float sc = fabsf(isc[j]);
#pragma unroll
                for (int h = 0; h < 2; h++) {
                    const int row = bM + warpM * 64 + mt * 16 + g + h * 8;
                    const float vo = acc[mt][nt][h * 2 + 0] + bo;
                    const float vg = acc[mt][nt][h * 2 + 1] + bg;
                    Cf[(size_t)row * outN + j] = fast_sigmoid(vg) * vo * sc;
                }
                continue;
            }
            const int col = colBase + cg;
            const float b0 = bias[col], b1 = bias[col + 1];
#pragma unroll
            for (int h = 0; h < 2; h++) {
                const int row = bM + warpM * 64 + mt * 16 + g + h * 8;
                float v0 = acc[mt][nt][h * 2 + 0] + b0;
                float v1 = acc[mt][nt][h * 2 + 1] + b1;
                if (act == 1)      { v0 = v0 * normcdff(v0); v1 = v1 * normcdff(v1); }
                else if (act == 2) { v0 = fast_sigmoid(v0); v1 = fast_sigmoid(v1); }
                else if (act == 3) { v0 = 5.f * fast_sigmoid(v0); v1 = 5.f * fast_sigmoid(v1); }
                if (res) {
                    v0 += res[(size_t)row * outN + col];
                    v1 += res[(size_t)row * outN + col + 1];
                }
                if (Ch) {
                    *reinterpret_cast<__half2*>(Ch + (size_t)row * outN + col) =
                        __floats2half2_rn(v0, v1);
                } else {
                    *reinterpret_cast<float2*>(Cf + (size_t)row * outN + col) =
                        make_float2(v0, v1);
                }
            }
        }
    }
}

// ---------------- prep kernels -----------------------------------------------
__global__ void f2h_kernel(const float* __restrict__ src,
                           __half* __restrict__ dst, int n)
{
    const int i = blockIdx.x * blockDim.x + threadIdx.x;
    if (i < n) dst[i] = __float2half_rn(src[i]);
}

__global__ void transpose4_h_kernel(const float* __restrict__ wOmega,
                                    const float* __restrict__ wGate,
                                    const float* __restrict__ wMag,
                                    const float* __restrict__ wP1,
                                    __half* __restrict__ Wt)
{
    __shared__ float t[32][33];
    const int z = blockIdx.z;
    const float* W = (z == 0) ? wOmega : (z == 1) ? wGate : (z == 2) ? wMag : wP1;
    const int k0 = blockIdx.y * 32, n0 = blockIdx.x * 32;
    t[threadIdx.y][threadIdx.x] = W[(size_t)(k0 + threadIdx.y) * D_ + n0 + threadIdx.x];
    __syncthreads();
    const int n = n0 + threadIdx.y;
    const int r = (z == 0) ? 2 * n : (z == 1) ? 2 * n + 1
                : (z == 2) ? 2 * D_ + n : 3 * D_ + n;
    Wt[(size_t)r * D_ + k0 + threadIdx.x] =
        __float2half_rn(t[threadIdx.x][threadIdx.y]);
}

__global__ void transpose_h_kernel(const float* __restrict__ W,
                                   __half* __restrict__ Wt, int K, int N)
{
    __shared__ float t[32][33];
    const int k0 = blockIdx.y * 32, n0 = blockIdx.x * 32;
    t[threadIdx.y][threadIdx.x] = W[(size_t)(k0 + threadIdx.y) * N + n0 + threadIdx.x];
    __syncthreads();
    Wt[(size_t)(n0 + threadIdx.y) * K + k0 + threadIdx.x] =
        __float2half_rn(t[threadIdx.x][threadIdx.y]);
}

// ---------------- scan kernels ----------------------------------------------
// float2: 2 d's per thread
__global__ void chunk_gsum_kernel(const float* __restrict__ gated,
                                  float* __restrict__ gsum)
{
    const int t = blockIdx.x * blockDim.x + threadIdx.x;
    if (t >= B_ * NCH_ * (D_ / 2)) return;
    const int d = (t % (D_ / 2)) * 2;
    const int c = (t / (D_ / 2)) % NCH_;
    const int b = t / ((D_ / 2) * NCH_);
    size_t idx = ((size_t)(b * S_ + c * CH_)) * D_ + d;
    float s0 = 0.f, s1 = 0.f;
    for (int s = 0; s < CH_; s++, idx += D_) {
        const float2 v = *reinterpret_cast<const float2*>(gated + idx);
        s0 += v.x;
        s1 += v.y;
    }
    const int co = (b * NCH_ + c) * D_ + d;
    gsum[co] = s0;
    gsum[co + 1] = s1;
}

__global__ void chunk_scan_kernel(float* __restrict__ v)
{
    const int t = blockIdx.x * blockDim.x + threadIdx.x;
    if (t >= B_ * D_) return;
    const int d = t % D_;
    const int b = t / D_;
    float run = 0.f;
    for (int c = 0; c < NCH_; c++) {
        const int i = (b * NCH_ + c) * D_ + d;
        const float x = v[i];
        v[i] = run;
        run += x;
    }
}

__global__ void chunk_scan3_kernel(float* __restrict__ v0,
                                   float* __restrict__ v1,
                                   float* __restrict__ v2)
{
    const int t = blockIdx.x * blockDim.x + threadIdx.x;
    const int total = B_ * D_;
    if (t >= 3 * total) return;
    float* v = (t < total) ? v0 : (t < 2 * total) ? v1 : v2;
    const int r = t % total;
    const int d = r % D_;
    const int b = r / D_;
    float run = 0.f;
    for (int c = 0; c < NCH_; c++) {
        const int i = (b * NCH_ + c) * D_ + d;
        const float x = v[i];
        v[i] = run;
        run += x;
    }
}

// phase 2: 2 d's per thread, fast sincos, per-chunk memory sums
__global__ void phi_mem_kernel(const float* __restrict__ gated,
                               float* __restrict__ phii,   // in: phi_init, out: sin(phi)
                               const float* __restrict__ mag,
                               const float* __restrict__ x,
                               const float* __restrict__ gsum,
                               float* __restrict__ cosphi,
                               float* __restrict__ rsum,
                               float* __restrict__ isum,
                               float* __restrict__ msum)
{
    const int t = blockIdx.x * blockDim.x + threadIdx.x;
    if (t >= B_ * NCH_ * (D_ / 2)) return;
    const int d = (t % (D_ / 2)) * 2;
    const int c = (t / (D_ / 2)) % NCH_;
    const int b = t / ((D_ / 2) * NCH_);
    const int co = (b * NCH_ + c) * D_ + d;

    float run0 = gsum[co], run1 = gsum[co + 1];
    float tR0 = 0.f, tI0 = 0.f, tM0 = 0.f;
    float tR1 = 0.f, tI1 = 0.f, tM1 = 0.f;
    size_t idx = ((size_t)(b * S_ + c * CH_)) * D_ + d;
    for (int s = 0; s < CH_; s++, idx += D_) {
        const float2 gv = *reinterpret_cast<const float2*>(gated + idx);
        const float2 pi = *reinterpret_cast<const float2*>(phii + idx);
        const float2 mg = *reinterpret_cast<const float2*>(mag + idx);
        const float2 xv = *reinterpret_cast<const float2*>(x + idx);
        run0 += gv.x;
        run1 += gv.y;
        const float p0 = pi.x + run0;
        const float p1 = pi.y + run1;
        float sp0, cp0, sp1, cp1;
        __sincosf(p0, &sp0, &cp0);
        __sincosf(p1, &sp1, &cp1);
        *reinterpret_cast<float2*>(cosphi + idx) = make_float2(cp0, cp1);
        *reinterpret_cast<float2*>(phii + idx) = make_float2(sp0, sp1);
        const float wc0 = mg.x * xv.x;
        const float wc1 = mg.y * xv.y;
        tR0 += wc0 * cp0;  tI0 += wc0 * sp0;  tM0 += mg.x;
        tR1 += wc1 * cp1;  tI1 += wc1 * sp1;  tM1 += mg.y;
    }
    rsum[co] = tR0;  rsum[co + 1] = tR1;
    isum[co] = tI0;  isum[co + 1] = tI1;
    msum[co] = tM0;  msum[co + 1] = tM1;
}

// ---------------- ctx: 2 d's per thread, half2 stores ------------------------
__global__ void ctx_kernel(const float* __restrict__ cosphi,
                           const float* __restrict__ sinphi,
                           const float* __restrict__ mag,
                           const float* __restrict__ x,
                           const float* __restrict__ rsum,
                           const float* __restrict__ isum,
                           const float* __restrict__ msum,
                           __half* __restrict__ ctx)
{
    const int t = blockIdx.x * blockDim.x + threadIdx.x;
    if (t >= B_ * NCH_ * (D_ / 2)) return;
    const int d = (t % (D_ / 2)) * 2;
    const int c = (t / (D_ / 2)) % NCH_;
    const int b = t / ((D_ / 2) * NCH_);
    const int co = (b * NCH_ + c) * D_ + d;

    float R0 = rsum[co], I0 = isum[co], M0 = msum[co];
    float R1 = rsum[co + 1], I1 = isum[co + 1], M1 = msum[co + 1];
    int tok = b * S_ + c * CH_;
    size_t idx = (size_t)tok * D_ + d;
    for (int s = 0; s < CH_; s++, idx += D_, tok++) {
        const float2 cp = *reinterpret_cast<const float2*>(cosphi + idx);
        const float2 sp = *reinterpret_cast<const float2*>(sinphi + idx);
        const float2 mg = *reinterpret_cast<const float2*>(mag + idx);
        const float2 xv = *reinterpret_cast<const float2*>(x + idx);

        R0 += mg.x * xv.x * cp.x;  I0 += mg.x * xv.x * sp.x;  M0 += mg.x;
        R1 += mg.y * xv.y * cp.y;  I1 += mg.y * xv.y * sp.y;  M1 += mg.y;
        const float inv0 = rsqrtf(M0 + 1e-8f);
        const float inv1 = rsqrtf(M1 + 1e-8f);
        const float mr0 = R0 * inv0, mi0 = I0 * inv0;
        const float mr1 = R1 * inv1, mi1 = I1 * inv1;

        const size_t cb = (size_t)tok * (4 * D_);
        *reinterpret_cast<__half2*>(ctx + cb + d) =
            __floats2half2_rn(xv.x * cp.x, xv.y * cp.y);
        *reinterpret_cast<__half2*>(ctx + cb + D_ + d) =
            __floats2half2_rn(xv.x * sp.x, xv.y * sp.y);
        *reinterpret_cast<__half2*>(ctx + cb + 2 * D_ + d) =
            __floats2half2_rn(mr0 * cp.x + mi0 * sp.x, mr1 * cp.y + mi1 * sp.y);
        *reinterpret_cast<__half2*>(ctx + cb + 3 * D_ + d) =
            __floats2half2_rn(mi0 * cp.x - mr0 * sp.x, mi1 * cp.y - mr1 * sp.y);
    }
}

// ---------------- LayerNorm in-place on half buffer --------------------------
__inline__ __device__ float warpSum(float v)
{
#pragma unroll
    for (int o = 16; o; o >>= 1) v += __shfl_xor_sync(0xffffffff, v, o);
    return v;
}

__global__ __launch_bounds__(256) void ln_kernel(__half* __restrict__ ctx,
                                                 const float* __restrict__ gam,
                                                 const float* __restrict__ bet)
{
    const int tok = blockIdx.x;
    __half2* row2 = reinterpret_cast<__half2*>(ctx + (size_t)tok * (4 * D_));
    float s = 0.f, s2 = 0.f;
    for (int i = threadIdx.x; i < 2 * D_; i += 256) {
        const float2 v = __half22float2(row2[i]);
        s += v.x + v.y;
        s2 += v.x * v.x + v.y * v.y;
    }
    s = warpSum(s);
    s2 = warpSum(s2);
    __shared__ float shs[8], shs2[8];
    const int wid = threadIdx.x >> 5, lane = threadIdx.x & 31;
    if (lane == 0) { shs[wid] = s; shs2[wid] = s2; }
    __syncthreads();
    s = 0.f; s2 = 0.f;
#pragma unroll
    for (int w = 0; w < 8; w++) { s += shs[w]; s2 += shs2[w]; }
    const float mu = s * (1.f / (4 * D_));
    const float var = s2 * (1.f / (4 * D_)) - mu * mu;
    const float inv = rsqrtf(var + 1e-5f);
    for (int i = threadIdx.x; i < 2 * D_; i += 256) {
        const float2 v = __half22float2(row2[i]);
        row2[i] = __floats2half2_rn((v.x - mu) * inv * gam[2 * i] + bet[2 * i],
                                    (v.y - mu) * inv * gam[2 * i + 1] + bet[2 * i + 1]);
    }
}

// ---------------- launch ----------------------------------------------------
extern "C" void kernel_launch(void* const* d_in, const int* in_sizes, int n_in,
                              void* d_out, int out_size)
{
    const float* x       = (const float*)d_in[0];
    const float* w_omega = (const float*)d_in[1];
    const float* b_omega = (const float*)d_in[2];
    const float* w_p1    = (const float*)d_in[3];
    const float* b_p1    = (const float*)d_in[4];
    const float* w_p2    = (const float*)d_in[5];
    const float* b_p2    = (const float*)d_in[6];
    const float* w_gate  = (const float*)d_in[7];
    const float* b_gate  = (const float*)d_in[8];
    const float* iscale  = (const float*)d_in[9];
    const float* w_mag   = (const float*)d_in[10];
    const float* b_mag   = (const float*)d_in[11];
    const float* ln_g    = (const float*)d_in[12];
    const float* ln_b    = (const float*)d_in[13];
    const float* w_o1    = (const float*)d_in[14];
    const float* b_o1    = (const float*)d_in[15];
    const float* w_o2    = (const float*)d_in[16];
    const float* b_o2    = (const float*)d_in[17];
    float* out = (float*)d_out;

    float *p_gated, *p_mag, *p_phii, *p_cos;
    float *p_gsum, *p_rsum, *p_isum, *p_msum;
    __half *p_xh, *p_p1h, *p_ctxh, *p_h1h, *p_wh, *p_wo1h, *p_wo2h;
    cudaGetSymbolAddress((void**)&p_gated, g_gated);
    cudaGetSymbolAddress((void**)&p_mag,   g_mag);
    cudaGetSymbolAddress((void**)&p_phii,  g_phii);
    cudaGetSymbolAddress((void**)&p_cos,   g_cos);
    cudaGetSymbolAddress((void**)&p_xh,    g_xh);
    cudaGetSymbolAddress((void**)&p_p1h,   g_p1h);
    cudaGetSymbolAddress((void**)&p_ctxh,  g_ctxh);
    cudaGetSymbolAddress((void**)&p_h1h,   g_h1h);
    cudaGetSymbolAddress((void**)&p_wh,    g_wh);
    cudaGetSymbolAddress((void**)&p_wo1h,  g_wo1h);
    cudaGetSymbolAddress((void**)&p_wo2h,  g_wo2h);
    cudaGetSymbolAddress((void**)&p_gsum,  g_gsum);
    cudaGetSymbolAddress((void**)&p_rsum,  g_rsum);
    cudaGetSymbolAddress((void**)&p_isum,  g_isum);
    cudaGetSymbolAddress((void**)&p_msum,  g_msum);

    static bool attr_set = false;
    if (!attr_set) {
        cudaFuncSetAttribute(mma_gemm, cudaFuncAttributeMaxDynamicSharedMemorySize, SMEM_GEMM);
        attr_set = true;
    }

    const dim3 blk(256);
    const dim3 tb(32, 32);

    // 0: x -> half
    f2h_kernel<<<(M_ * D_) / 256, blk>>>(x, p_xh, M_ * D_);
    // 1: fused interleaved transpose of proj weights
    transpose4_h_kernel<<<dim3(D_ / 32, D_ / 32, 4), tb>>>(w_omega, w_gate, w_mag, w_p1, p_wh);
    // 2: p2 weight
    transpose_h_kernel<<<dim3(D_ / 32, D_ / 32), tb>>>(w_p2, p_wh + 4 * (size_t)D_ * D_, D_, D_);

    // 3: fused projection GEMM: [16384,1024] @ [1024,4096]
    {
        Outs o;
        o.f[0] = p_gated; o.h[0] = nullptr; o.bias[0] = b_omega; o.act[0] = 4;
        o.f[1] = p_gated; o.h[1] = nullptr; o.bias[1] = b_omega; o.act[1] = 4;
        o.f[2] = p_mag;   o.h[2] = nullptr; o.bias[2] = b_mag;   o.act[2] = 3;
        o.f[3] = nullptr; o.h[3] = p_p1h;   o.bias[3] = b_p1;    o.act[3] = 1;
        dim3 g((4 * D_) / 128, M_ / 128);
        mma_gemm<<<g, blk, SMEM_GEMM>>>(p_xh, p_wh, nullptr, o, D_, 4 * D_, 10, D_,
                                        iscale, b_gate);
    }

    // remaining weight prep (off critical path)
    transpose_h_kernel<<<dim3((2 * D_) / 32, (4 * D_) / 32), tb>>>(w_o1, p_wo1h, 4 * D_, 2 * D_);
    transpose_h_kernel<<<dim3(D_ / 32, (2 * D_) / 32), tb>>>(w_o2, p_wo2h, 2 * D_, D_);

    // p2 GEMM
    {
        Outs o;
        o.f[0] = p_phii; o.h[0] = nullptr; o.bias[0] = b_p2; o.act[0] = 0;
        o.f[1] = o.f[2] = o.f[3] = nullptr;
        o.h[1] = o.h[2] = o.h[3] = nullptr;
        o.bias[1] = o.bias[2] = o.bias[3] = b_p2;
        o.act[1] = o.act[2] = o.act[3] = 0;
        dim3 g(D_ / 128, M_ / 128);
        mma_gemm<<<g, blk, SMEM_GEMM>>>(p_p1h, p_wh + 4 * (size_t)D_ * D_, nullptr, o,
                                        D_, D_, 30, D_, nullptr, nullptr);
    }

    // --- hierarchical scans ---
    const int nwork = B_ * NCH_ * D_;
    chunk_gsum_kernel<<<(nwork / 2) / 256, blk>>>(p_gated, p_gsum);
    chunk_scan_kernel<<<(B_ * D_) / 256, blk>>>(p_gsum);
    phi_mem_kernel<<<(nwork / 2) / 256, blk>>>(p_gated, p_phii, p_mag, x, p_gsum,
                                               p_cos, p_rsum, p_isum, p_msum);
    chunk_scan3_kernel<<<(3 * B_ * D_) / 256, blk>>>(p_rsum, p_isum, p_msum);
    ctx_kernel<<<(nwork / 2) / 256, blk>>>(p_cos, p_phii, p_mag, x,
                                           p_rsum, p_isum, p_msum, p_ctxh);

    // --- LayerNorm in place (half) ---
    ln_kernel<<<M_, blk>>>(p_ctxh, ln_g, ln_b);

    // --- output MLP ---
    {
        Outs o1o;
        o1o.f[0] = nullptr; o1o.h[0] = p_h1h; o1o.bias[0] = b_o1; o1o.act[0] = 1;
        o1o.f[1] = o1o.f[2] = o1o.f[3] = nullptr;
        o1o.h[1] = o1o.h[2] = o1o.h[3] = nullptr;
        o1o.bias[1] = o1o.bias[2] = o1o.bias[3] = b_o1;
        o1o.act[1] = o1o.act[2] = o1o.act[3] = 0;
        dim3 g1((2 * D_) / 128, M_ / 128);
        mma_gemm<<<g1, blk, SMEM_GEMM>>>(p_ctxh, p_wo1h, nullptr, o1o, 4 * D_, 2 * D_, 30, 2 * D_,
                                         nullptr, nullptr);

        Outs o2o;
        o2o.f[0] = out; o2o.h[0] = nullptr; o2o.bias[0] = b_o2; o2o.act[0] = 0;
        o2o.f[1] = o2o.f[2] = o2o.f[3] = nullptr;
        o2o.h[1] = o2o.h[2] = o2o.h[3] = nullptr;
        o2o.bias[1] = o2o.bias[2] = o2o.bias[3] = b_o2;
        o2o.act[1] = o2o.act[2] = o2o.act[3] = 0;
        dim3 g2(D_ / 128, M_ / 128);
        mma_gemm<<<g2, blk, SMEM_GEMM>>>(p_h1h, p_wo2h, x, o2o, 2 * D_, D_, 30, D_,
                                         nullptr, nullptr);
    }
}

// round 15
// speedup vs baseline: 1.1035x; 1.0086x over previous
#include <cuda_runtime.h>
#include <cuda_fp16.h>
#include <math.h>
#include <stdint.h>

// Problem dims
#define B_   4
#define S_   4096
#define D_   1024
#define M_   16384
#define CH_  256
#define NCH_ 16

// ---------------- scratch ---------------------------------------------------
__device__ float g_gated[(size_t)M_ * D_];   // sigmoid(gate)*omega*|iscale|
__device__ float g_mag  [(size_t)M_ * D_];
__device__ float g_phii [(size_t)M_ * D_];   // phi_init, then sin(phi)
__device__ float g_cos  [(size_t)M_ * D_];   // cos(phi)
__device__ __half g_xh  [(size_t)M_ * D_];
__device__ __half g_p1h [(size_t)M_ * D_];
__device__ __half g_ctxh[(size_t)M_ * 4 * D_];   // ctx (half), LN in-place
__device__ __half g_h1h [(size_t)M_ * 2 * D_];
__device__ __half g_wh  [5 * (size_t)D_ * D_];   // fused proj B (interleaved) + p2
__device__ __half g_wo1h[(size_t)(2 * D_) * (4 * D_)];
__device__ __half g_wo2h[(size_t)D_ * (2 * D_)];
__device__ float g_gsum [B_ * NCH_ * D_];
__device__ float g_rsum [B_ * NCH_ * D_];
__device__ float g_isum [B_ * NCH_ * D_];
__device__ float g_msum [B_ * NCH_ * D_];

// ---------------- PTX helpers ------------------------------------------------
__device__ __forceinline__ uint32_t smem_u32(const void* p) {
    uint32_t a;
    asm("{ .reg .u64 t; cvta.to.shared.u64 t, %1; cvt.u32.u64 %0, t; }" : "=r"(a) : "l"(p));
    return a;
}

__device__ __forceinline__ float fast_sigmoid(float v) {
    return 1.f / (1.f + __expf(-v));
}

#define CP_ASYNC16(s, g) asm volatile("cp.async.cg.shared.global [%0], [%1], 16;" :: "r"(s), "l"(g) : "memory")
#define CP_COMMIT()      asm volatile("cp.async.commit_group;" ::: "memory")
#define CP_WAIT1()       asm volatile("cp.async.wait_group 1;" ::: "memory")

#define LDSM4(r0, r1, r2, r3, a)                                                \
    asm volatile("ldmatrix.sync.aligned.m8n8.x4.shared.b16 {%0,%1,%2,%3}, [%4];"\
        : "=r"(r0), "=r"(r1), "=r"(r2), "=r"(r3) : "r"(a))

#define MMA16816(d, a, b0, b1)                                                  \
    asm volatile("mma.sync.aligned.m16n8k16.row.col.f32.f16.f16.f32 "           \
        "{%0,%1,%2,%3}, {%4,%5,%6,%7}, {%8,%9}, {%0,%1,%2,%3};"                 \
        : "+f"((d)[0]), "+f"((d)[1]), "+f"((d)[2]), "+f"((d)[3])                \
        : "r"((a)[0]), "r"((a)[1]), "r"((a)[2]), "r"((a)[3]),                   \
          "r"(b0), "r"(b1))

// ---------------- fp16 tensor-core GEMM --------------------------------------
#define NSTAGE 3
#define STG_BYTES 32768
#define SMEM_GEMM (NSTAGE * STG_BYTES)

struct Outs {
    float* f[4];
    __half* h[4];
    const float* bias[4];
    int act[4];
};

__global__ __launch_bounds__(256, 2) void mma_gemm(
    const __half* __restrict__ A, const __half* __restrict__ Bt,
    const float* __restrict__ res, Outs o, int K, int N, int blkShift, int outN,
    const float* __restrict__ isc, const float* __restrict__ bias2)
{
    extern __shared__ char smraw[];
    const uint32_t tileBase = smem_u32(smraw);
    const int tid = threadIdx.x;
    const int lane = tid & 31;
    const int wid = tid >> 5;
    const int warpM = wid & 1;
    const int warpN = wid >> 1;
    const int bM = blockIdx.y * 128;
    const int bN = blockIdx.x * 128;
    const int kIters = K >> 6;

    const int lr0 = tid >> 3;
    const int lcc = tid & 7;
    const __half* aSrc0 = A + (size_t)(bM + lr0) * K + lcc * 8;
    const __half* bSrc0 = Bt + (size_t)(bN + lr0) * K + lcc * 8;
    const uint32_t ldst0 = lr0 * 128 + ((lcc ^ (lr0 & 7)) << 4);

    uint32_t pA[4], pB[2];
#pragma unroll
    for (int mt = 0; mt < 4; mt++) {
        const int row = warpM * 64 + mt * 16 + (lane & 15);
        pA[mt] = row * 128 + ((((lane >> 4) ^ row) & 7) << 4);
    }
#pragma unroll
    for (int bt = 0; bt < 2; bt++) {
        const int row = warpN * 32 + bt * 16 + (lane & 7) + ((lane & 16) >> 1);
        pB[bt] = 16384 + row * 128 + (((((lane >> 3) & 1) ^ row) & 7) << 4);
    }

    float acc[4][4][4];
#pragma unroll
    for (int i = 0; i < 4; i++)
#pragma unroll
        for (int j = 0; j < 4; j++)
#pragma unroll
            for (int e = 0; e < 4; e++) acc[i][j][e] = 0.f;

    auto load_stage = [&](int kt, int slot) {
        const uint32_t dst = tileBase + slot * STG_BYTES + ldst0;
        const __half* a = aSrc0 + (kt << 6);
        const __half* b = bSrc0 + (kt << 6);
#pragma unroll
        for (int j = 0; j < 4; j++)
            CP_ASYNC16(dst + j * 4096, a + (size_t)j * 32 * K);
#pragma unroll
        for (int j = 0; j < 4; j++)
            CP_ASYNC16(dst + 16384 + j * 4096, b + (size_t)j * 32 * K);
        CP_COMMIT();
    };

    load_stage(0, 0);
    load_stage(1, 1);

    int slot = 0, slotNxt = 2;
    for (int kt = 0; kt < kIters; kt++) {
        CP_WAIT1();
        __syncthreads();
        if (kt + 2 < kIters) load_stage(kt + 2, slotNxt);

        const uint32_t sBase = tileBase + slot * STG_BYTES;
        uint32_t qA[4], qB[2];
#pragma unroll
        for (int mt = 0; mt < 4; mt++) qA[mt] = sBase + pA[mt];
#pragma unroll
        for (int bt = 0; bt < 2; bt++) qB[bt] = sBase + pB[bt];

#pragma unroll
        for (int ks = 0; ks < 4; ks++) {
            const uint32_t xo = ks << 5;
            uint32_t a[4][4], b[8];
#pragma unroll
            for (int mt = 0; mt < 4; mt++)
                LDSM4(a[mt][0], a[mt][1], a[mt][2], a[mt][3], qA[mt] ^ xo);
#pragma unroll
            for (int bt = 0; bt < 2; bt++)
                LDSM4(b[bt * 4 + 0], b[bt * 4 + 1], b[bt * 4 + 2], b[bt * 4 + 3],
                      qB[bt] ^ xo);
#pragma unroll
            for (int mt = 0; mt < 4; mt++)
#pragma unroll
                for (int nt = 0; nt < 4; nt++)
                    MMA16816(acc[mt][nt], a[mt],
                             b[(nt >> 1) * 4 + (nt & 1) * 2],
                             b[(nt >> 1) * 4 + (nt & 1) * 2 + 1]);
        }
        if (++slot == NSTAGE) slot = 0;
        if (++slotNxt == NSTAGE) slotNxt = 0;
    }

    // epilogue
    int blk = bN >> blkShift;
    if (blk > 3) blk = 3;
    const int act = o.act[blk];
    float* Cf = o.f[blk];
    __half* Ch = o.h[blk];
    const float* bias = o.bias[blk];
    const int colBase = bN & (outN - 1);
    const int g = lane >> 2, q = lane & 3;
#pragma unroll
    for (int mt = 0; mt < 4; mt++) {
#pragma unroll
        for (int nt = 0; nt < 4; nt++) {
            const int cg = warpN * 32 + nt * 8 + q * 2;
            if (act == 4) {
                const int j = (bN + cg) >> 1;
                const float bo = bias[j];
                const float bg = bias2[j];
                const float sc = fabsf(isc[j]);
#pragma unroll
                for (int h = 0; h < 2; h++) {
                    const int row = bM + warpM * 64 + mt * 16 + g + h * 8;
                    const float vo = acc[mt][nt][h * 2 + 0] + bo;
                    const float vg = acc[mt][nt][h * 2 + 1] + bg;
                    Cf[(size_t)row * outN + j] = fast_sigmoid(vg) * vo * sc;
                }
                continue;
            }
            const int col = colBase + cg;
            const float b0 = bias[col], b1 = bias[col + 1];
#pragma unroll
            for (int h = 0; h < 2; h++) {
                const int row = bM + warpM * 64 + mt * 16 + g + h * 8;
                float v0 = acc[mt][nt][h * 2 + 0] + b0;
                float v1 = acc[mt][nt][h * 2 + 1] + b1;
                if (act == 1)      { v0 = v0 * normcdff(v0); v1 = v1 * normcdff(v1); }
                else if (act == 2) { v0 = fast_sigmoid(v0); v1 = fast_sigmoid(v1); }
                else if (act == 3) { v0 = 5.f * fast_sigmoid(v0); v1 = 5.f * fast_sigmoid(v1); }
                if (res) {
                    v0 += res[(size_t)row * outN + col];
                    v1 += res[(size_t)row * outN + col + 1];
                }
                if (Ch) {
                    *reinterpret_cast<__half2*>(Ch + (size_t)row * outN + col) =
                        __floats2half2_rn(v0, v1);
                } else {
                    *reinterpret_cast<float2*>(Cf + (size_t)row * outN + col) =
                        make_float2(v0, v1);
                }
            }
        }
    }
}

// ---------------- prep kernels -----------------------------------------------
__global__ void f2h_kernel(const float* __restrict__ src,
                           __half* __restrict__ dst, int n)
{
    const int i = blockIdx.x * blockDim.x + threadIdx.x;
    if (i < n) dst[i] = __float2half_rn(src[i]);
}

__global__ void transpose4_h_kernel(const float* __restrict__ wOmega,
                                    const float* __restrict__ wGate,
                                    const float* __restrict__ wMag,
                                    const float* __restrict__ wP1,
                                    __half* __restrict__ Wt)
{
    __shared__ float t[32][33];
    const int z = blockIdx.z;
    const float* W = (z == 0) ? wOmega : (z == 1) ? wGate : (z == 2) ? wMag : wP1;
    const int k0 = blockIdx.y * 32, n0 = blockIdx.x * 32;
    t[threadIdx.y][threadIdx.x] = W[(size_t)(k0 + threadIdx.y) * D_ + n0 + threadIdx.x];
    __syncthreads();
    const int n = n0 + threadIdx.y;
    const int r = (z == 0) ? 2 * n : (z == 1) ? 2 * n + 1
                : (z == 2) ? 2 * D_ + n : 3 * D_ + n;
    Wt[(size_t)r * D_ + k0 + threadIdx.x] =
        __float2half_rn(t[threadIdx.x][threadIdx.y]);
}

__global__ void transpose_h_kernel(const float* __restrict__ W,
                                   __half* __restrict__ Wt, int K, int N)
{
    __shared__ float t[32][33];
    const int k0 = blockIdx.y * 32, n0 = blockIdx.x * 32;
    t[threadIdx.y][threadIdx.x] = W[(size_t)(k0 + threadIdx.y) * N + n0 + threadIdx.x];
    __syncthreads();
    Wt[(size_t)(n0 + threadIdx.y) * K + k0 + threadIdx.x] =
        __float2half_rn(t[threadIdx.x][threadIdx.y]);
}

// ---------------- scan kernels ----------------------------------------------
__global__ void chunk_gsum_kernel(const float* __restrict__ gated,
                                  float* __restrict__ gsum)
{
    const int t = blockIdx.x * blockDim.x + threadIdx.x;
    if (t >= B_ * NCH_ * (D_ / 2)) return;
    const int d = (t % (D_ / 2)) * 2;
    const int c = (t / (D_ / 2)) % NCH_;
    const int b = t / ((D_ / 2) * NCH_);
    size_t idx = ((size_t)(b * S_ + c * CH_)) * D_ + d;
    float s0 = 0.f, s1 = 0.f;
    for (int s = 0; s < CH_; s++, idx += D_) {
        const float2 v = *reinterpret_cast<const float2*>(gated + idx);
        s0 += v.x;
        s1 += v.y;
    }
    const int co = (b * NCH_ + c) * D_ + d;
    gsum[co] = s0;
    gsum[co + 1] = s1;
}

__global__ void chunk_scan_kernel(float* __restrict__ v)
{
    const int t = blockIdx.x * blockDim.x + threadIdx.x;
    if (t >= B_ * D_) return;
    const int d = t % D_;
    const int b = t / D_;
    float run = 0.f;
    for (int c = 0; c < NCH_; c++) {
        const int i = (b * NCH_ + c) * D_ + d;
        const float x = v[i];
        v[i] = run;
        run += x;
    }
}

__global__ void chunk_scan3_kernel(float* __restrict__ v0,
                                   float* __restrict__ v1,
                                   float* __restrict__ v2)
{
    const int t = blockIdx.x * blockDim.x + threadIdx.x;
    const int total = B_ * D_;
    if (t >= 3 * total) return;
    float* v = (t < total) ? v0 : (t < 2 * total) ? v1 : v2;
    const int r = t % total;
    const int d = r % D_;
    const int b = r / D_;
    float run = 0.f;
    for (int c = 0; c < NCH_; c++) {
        const int i = (b * NCH_ + c) * D_ + d;
        const float x = v[i];
        v[i] = run;
        run += x;
    }
}

__global__ void phi_mem_kernel(const float* __restrict__ gated,
                               float* __restrict__ phii,   // in: phi_init, out: sin(phi)
                               const float* __restrict__ mag,
                               const float* __restrict__ x,
                               const float* __restrict__ gsum,
                               float* __restrict__ cosphi,
                               float* __restrict__ rsum,
                               float* __restrict__ isum,
                               float* __restrict__ msum)
{
    const int t = blockIdx.x * blockDim.x + threadIdx.x;
    if (t >= B_ * NCH_ * (D_ / 2)) return;
    const int d = (t % (D_ / 2)) * 2;
    const int c = (t / (D_ / 2)) % NCH_;
    const int b = t / ((D_ / 2) * NCH_);
    const int co = (b * NCH_ + c) * D_ + d;

    float run0 = gsum[co], run1 = gsum[co + 1];
    float tR0 = 0.f, tI0 = 0.f, tM0 = 0.f;
    float tR1 = 0.f, tI1 = 0.f, tM1 = 0.f;
    size_t idx = ((size_t)(b * S_ + c * CH_)) * D_ + d;
    for (int s = 0; s < CH_; s++, idx += D_) {
        const float2 gv = *reinterpret_cast<const float2*>(gated + idx);
        const float2 pi = *reinterpret_cast<const float2*>(phii + idx);
        const float2 mg = *reinterpret_cast<const float2*>(mag + idx);
        const float2 xv = *reinterpret_cast<const float2*>(x + idx);
        run0 += gv.x;
        run1 += gv.y;
        const float p0 = pi.x + run0;
        const float p1 = pi.y + run1;
        float sp0, cp0, sp1, cp1;
        __sincosf(p0, &sp0, &cp0);
        __sincosf(p1, &sp1, &cp1);
        *reinterpret_cast<float2*>(cosphi + idx) = make_float2(cp0, cp1);
        *reinterpret_cast<float2*>(phii + idx) = make_float2(sp0, sp1);
        const float wc0 = mg.x * xv.x;
        const float wc1 = mg.y * xv.y;
        tR0 += wc0 * cp0;  tI0 += wc0 * sp0;  tM0 += mg.x;
        tR1 += wc1 * cp1;  tI1 += wc1 * sp1;  tM1 += mg.y;
    }
    rsum[co] = tR0;  rsum[co + 1] = tR1;
    isum[co] = tI0;  isum[co + 1] = tI1;
    msum[co] = tM0;  msum[co + 1] = tM1;
}

__global__ void ctx_kernel(const float* __restrict__ cosphi,
                           const float* __restrict__ sinphi,
                           const float* __restrict__ mag,
                           const float* __restrict__ x,
                           const float* __restrict__ rsum,
                           const float* __restrict__ isum,
                           const float* __restrict__ msum,
                           __half* __restrict__ ctx)
{
    const int t = blockIdx.x * blockDim.x + threadIdx.x;
    if (t >= B_ * NCH_ * (D_ / 2)) return;
    const int d = (t % (D_ / 2)) * 2;
    const int c = (t / (D_ / 2)) % NCH_;
    const int b = t / ((D_ / 2) * NCH_);
    const int co = (b * NCH_ + c) * D_ + d;

    float R0 = rsum[co], I0 = isum[co], M0 = msum[co];
    float R1 = rsum[co + 1], I1 = isum[co + 1], M1 = msum[co + 1];
    int tok = b * S_ + c * CH_;
    size_t idx = (size_t)tok * D_ + d;
    for (int s = 0; s < CH_; s++, idx += D_, tok++) {
        const float2 cp = *reinterpret_cast<const float2*>(cosphi + idx);
        const float2 sp = *reinterpret_cast<const float2*>(sinphi + idx);
        const float2 mg = *reinterpret_cast<const float2*>(mag + idx);
        const float2 xv = *reinterpret_cast<const float2*>(x + idx);

        R0 += mg.x * xv.x * cp.x;  I0 += mg.x * xv.x * sp.x;  M0 += mg.x;
        R1 += mg.y * xv.y * cp.y;  I1 += mg.y * xv.y * sp.y;  M1 += mg.y;
        const float inv0 = rsqrtf(M0 + 1e-8f);
        const float inv1 = rsqrtf(M1 + 1e-8f);
        const float mr0 = R0 * inv0, mi0 = I0 * inv0;
        const float mr1 = R1 * inv1, mi1 = I1 * inv1;

        const size_t cb = (size_t)tok * (4 * D_);
        *reinterpret_cast<__half2*>(ctx + cb + d) =
            __floats2half2_rn(xv.x * cp.x, xv.y * cp.y);
        *reinterpret_cast<__half2*>(ctx + cb + D_ + d) =
            __floats2half2_rn(xv.x * sp.x, xv.y * sp.y);
        *reinterpret_cast<__half2*>(ctx + cb + 2 * D_ + d) =
            __floats2half2_rn(mr0 * cp.x + mi0 * sp.x, mr1 * cp.y + mi1 * sp.y);
        *reinterpret_cast<__half2*>(ctx + cb + 3 * D_ + d) =
            __floats2half2_rn(mi0 * cp.x - mr0 * sp.x, mi1 * cp.y - mr1 * sp.y);
    }
}

// ---------------- LayerNorm in-place on half buffer --------------------------
__inline__ __device__ float warpSum(float v)
{
#pragma unroll
    for (int o = 16; o; o >>= 1) v += __shfl_xor_sync(0xffffffff, v, o);
    return v;
}

__global__ __launch_bounds__(256) void ln_kernel(__half* __restrict__ ctx,
                                                 const float* __restrict__ gam,
                                                 const float* __restrict__ bet)
{
    const int tok = blockIdx.x;
    __half2* row2 = reinterpret_cast<__half2*>(ctx + (size_t)tok * (4 * D_));
    float s = 0.f, s2 = 0.f;
    for (int i = threadIdx.x; i < 2 * D_; i += 256) {
        const float2 v = __half22float2(row2[i]);
        s += v.x + v.y;
        s2 += v.x * v.x + v.y * v.y;
    }
    s = warpSum(s);
    s2 = warpSum(s2);
    __shared__ float shs[8], shs2[8];
    const int wid = threadIdx.x >> 5, lane = threadIdx.x & 31;
    if (lane == 0) { shs[wid] = s; shs2[wid] = s2; }
    __syncthreads();
    s = 0.f; s2 = 0.f;
#pragma unroll
    for (int w = 0; w < 8; w++) { s += shs[w]; s2 += shs2[w]; }
    const float mu = s * (1.f / (4 * D_));
    const float var = s2 * (1.f / (4 * D_)) - mu * mu;
    const float inv = rsqrtf(var + 1e-5f);
    for (int i = threadIdx.x; i < 2 * D_; i += 256) {
        const float2 v = __half22float2(row2[i]);
        row2[i] = __floats2half2_rn((v.x - mu) * inv * gam[2 * i] + bet[2 * i],
                                    (v.y - mu) * inv * gam[2 * i + 1] + bet[2 * i + 1]);
    }
}

// ---------------- launch ----------------------------------------------------
extern "C" void kernel_launch(void* const* d_in, const int* in_sizes, int n_in,
                              void* d_out, int out_size)
{
    const float* x       = (const float*)d_in[0];
    const float* w_omega = (const float*)d_in[1];
    const float* b_omega = (const float*)d_in[2];
    const float* w_p1    = (const float*)d_in[3];
    const float* b_p1    = (const float*)d_in[4];
    const float* w_p2    = (const float*)d_in[5];
    const float* b_p2    = (const float*)d_in[6];
    const float* w_gate  = (const float*)d_in[7];
    const float* b_gate  = (const float*)d_in[8];
    const float* iscale  = (const float*)d_in[9];
    const float* w_mag   = (const float*)d_in[10];
    const float* b_mag   = (const float*)d_in[11];
    const float* ln_g    = (const float*)d_in[12];
    const float* ln_b    = (const float*)d_in[13];
    const float* w_o1    = (const float*)d_in[14];
    const float* b_o1    = (const float*)d_in[15];
    const float* w_o2    = (const float*)d_in[16];
    const float* b_o2    = (const float*)d_in[17];
    float* out = (float*)d_out;

    float *p_gated, *p_mag, *p_phii, *p_cos;
    float *p_gsum, *p_rsum, *p_isum, *p_msum;
    __half *p_xh, *p_p1h, *p_ctxh, *p_h1h, *p_wh, *p_wo1h, *p_wo2h;
    cudaGetSymbolAddress((void**)&p_gated, g_gated);
    cudaGetSymbolAddress((void**)&p_mag,   g_mag);
    cudaGetSymbolAddress((void**)&p_phii,  g_phii);
    cudaGetSymbolAddress((void**)&p_cos,   g_cos);
    cudaGetSymbolAddress((void**)&p_xh,    g_xh);
    cudaGetSymbolAddress((void**)&p_p1h,   g_p1h);
    cudaGetSymbolAddress((void**)&p_ctxh,  g_ctxh);
    cudaGetSymbolAddress((void**)&p_h1h,   g_h1h);
    cudaGetSymbolAddress((void**)&p_wh,    g_wh);
    cudaGetSymbolAddress((void**)&p_wo1h,  g_wo1h);
    cudaGetSymbolAddress((void**)&p_wo2h,  g_wo2h);
    cudaGetSymbolAddress((void**)&p_gsum,  g_gsum);
    cudaGetSymbolAddress((void**)&p_rsum,  g_rsum);
    cudaGetSymbolAddress((void**)&p_isum,  g_isum);
    cudaGetSymbolAddress((void**)&p_msum,  g_msum);

    static bool init_done = false;
    static cudaStream_t s2;
    static cudaEvent_t e0, eProj, eS2;
    if (!init_done) {
        cudaFuncSetAttribute(mma_gemm, cudaFuncAttributeMaxDynamicSharedMemorySize, SMEM_GEMM);
        cudaStreamCreateWithFlags(&s2, cudaStreamNonBlocking);
        cudaEventCreateWithFlags(&e0,    cudaEventDisableTiming);
        cudaEventCreateWithFlags(&eProj, cudaEventDisableTiming);
        cudaEventCreateWithFlags(&eS2,   cudaEventDisableTiming);
        init_done = true;
    }

    const dim3 blk(256);
    const dim3 tb(32, 32);
    const int nwork = B_ * NCH_ * D_;

    // ---- fork: side stream handles o1/o2 weight transposes (input-only deps)
    cudaEventRecord(e0, 0);
    cudaStreamWaitEvent(s2, e0, 0);
    transpose_h_kernel<<<dim3((2 * D_) / 32, (4 * D_) / 32), tb, 0, s2>>>(w_o1, p_wo1h, 4 * D_, 2 * D_);
    transpose_h_kernel<<<dim3(D_ / 32, (2 * D_) / 32), tb, 0, s2>>>(w_o2, p_wo2h, 2 * D_, D_);

    // ---- main stream: prep -> proj GEMM
    f2h_kernel<<<(M_ * D_) / 256, blk>>>(x, p_xh, M_ * D_);
    transpose4_h_kernel<<<dim3(D_ / 32, D_ / 32, 4), tb>>>(w_omega, w_gate, w_mag, w_p1, p_wh);
    transpose_h_kernel<<<dim3(D_ / 32, D_ / 32), tb>>>(w_p2, p_wh + 4 * (size_t)D_ * D_, D_, D_);

    {
        Outs o;
        o.f[0] = p_gated; o.h[0] = nullptr; o.bias[0] = b_omega; o.act[0] = 4;
        o.f[1] = p_gated; o.h[1] = nullptr; o.bias[1] = b_omega; o.act[1] = 4;
        o.f[2] = p_mag;   o.h[2] = nullptr; o.bias[2] = b_mag;   o.act[2] = 3;
        o.f[3] = nullptr; o.h[3] = p_p1h;   o.bias[3] = b_p1;    o.act[3] = 1;
        dim3 g((4 * D_) / 128, M_ / 128);
        mma_gemm<<<g, blk, SMEM_GEMM>>>(p_xh, p_wh, nullptr, o, D_, 4 * D_, 10, D_,
                                        iscale, b_gate);
    }
    cudaEventRecord(eProj, 0);

    // ---- side stream: gsum + scan (need only gated), overlapping p2 GEMM
    cudaStreamWaitEvent(s2, eProj, 0);
    chunk_gsum_kernel<<<(nwork / 2) / 256, blk, 0, s2>>>(p_gated, p_gsum);
    chunk_scan_kernel<<<(B_ * D_) / 256, blk, 0, s2>>>(p_gsum);
    cudaEventRecord(eS2, s2);

    // ---- main stream: p2 GEMM (needs p1h from proj)
    {
        Outs o;
        o.f[0] = p_phii; o.h[0] = nullptr; o.bias[0] = b_p2; o.act[0] = 0;
        o.f[1] = o.f[2] = o.f[3] = nullptr;
        o.h[1] = o.h[2] = o.h[3] = nullptr;
        o.bias[1] = o.bias[2] = o.bias[3] = b_p2;
        o.act[1] = o.act[2] = o.act[3] = 0;
        dim3 g(D_ / 128, M_ / 128);
        mma_gemm<<<g, blk, SMEM_GEMM>>>(p_p1h, p_wh + 4 * (size_t)D_ * D_, nullptr, o,
                                        D_, D_, 30, D_, nullptr, nullptr);
    }

    // ---- join: phi_mem needs gsum (s2) + phii (main) + gated/mag (proj)
    cudaStreamWaitEvent(0, eS2, 0);

    phi_mem_kernel<<<(nwork / 2) / 256, blk>>>(p_gated, p_phii, p_mag, x, p_gsum,
                                               p_cos, p_rsum, p_isum, p_msum);
    chunk_scan3_kernel<<<(3 * B_ * D_) / 256, blk>>>(p_rsum, p_isum, p_msum);
    ctx_kernel<<<(nwork / 2) / 256, blk>>>(p_cos, p_phii, p_mag, x,
                                           p_rsum, p_isum, p_msum, p_ctxh);

    ln_kernel<<<M_, blk>>>(p_ctxh, ln_g, ln_b);

    // ---- output MLP (o1 weight ready via eS2 join; o2 weight too)
    {
        Outs o1o;
        o1o.f[0] = nullptr; o1o.h[0] = p_h1h; o1o.bias[0] = b_o1; o1o.act[0] = 1;
        o1o.f[1] = o1o.f[2] = o1o.f[3] = nullptr;
        o1o.h[1] = o1o.h[2] = o1o.h[3] = nullptr;
        o1o.bias[1] = o1o.bias[2] = o1o.bias[3] = b_o1;
        o1o.act[1] = o1o.act[2] = o1o.act[3] = 0;
        dim3 g1((2 * D_) / 128, M_ / 128);
        mma_gemm<<<g1, blk, SMEM_GEMM>>>(p_ctxh, p_wo1h, nullptr, o1o, 4 * D_, 2 * D_, 30, 2 * D_,
                                         nullptr, nullptr);

        Outs o2o;
        o2o.f[0] = out; o2o.h[0] = nullptr; o2o.bias[0] = b_o2; o2o.act[0] = 0;
        o2o.f[1] = o2o.f[2] = o2o.f[3] = nullptr;
        o2o.h[1] = o2o.h[2] = o2o.h[3] = nullptr;
        o2o.bias[1] = o2o.bias[2] = o2o.bias[3] = b_o2;
        o2o.act[1] = o2o.act[2] = o2o.act[3] = 0;
        dim3 g2(D_ / 128, M_ / 128);
        mma_gemm<<<g2, blk, SMEM_GEMM>>>(p_h1h, p_wo2h, x, o2o, 2 * D_, D_, 30, D_,
                                         nullptr, nullptr);
    }
}